// round 1
// baseline (speedup 1.0000x reference)
#include <cuda_runtime.h>
#include <math.h>

#define N_NODES 50000
#define N_EDGES 800000
#define NTOT    850000   // E + N self loops
#define NGRAPH  256
#define F_IN    64
#define HEADS   4
#define HC      256      // HEADS*F_IN
#define ODIM    128

// ---------------- scratch (device globals; no allocation) ----------------
__device__ float g_xh  [N_NODES * HC];   // x @ lin_w^T
__device__ float g_asrc[N_NODES * HEADS];
__device__ float g_adst[N_NODES * HEADS];
__device__ float g_amax[N_NODES * HEADS];
__device__ float g_den [N_NODES * HEADS];
__device__ float g_x2  [N_NODES * HC];   // GAT output (init to bias, atomically accumulated)
__device__ float g_sub [N_NODES * HC];   // GraphNorm centered
__device__ float g_h   [N_NODES * HC];   // after norm + relu
__device__ float g_cnt [NGRAPH];
__device__ float g_mean[NGRAPH * HC];
__device__ float g_var [NGRAPH * HC];
__device__ float g_gate[N_NODES];
__device__ float g_gmax[NGRAPH];
__device__ float g_gden[NGRAPH];
__device__ float g_pool[NGRAPH * HC];

__device__ __forceinline__ void atomicMaxF(float* addr, float val) {
    int* ia = (int*)addr;
    int old = *ia;
    while (__int_as_float(old) < val) {
        int assumed = old;
        old = atomicCAS(ia, assumed, __float_as_int(val));
        if (old == assumed) break;
    }
}

// ---------------- init ----------------
__global__ void k_init(const float* __restrict__ gat_bias) {
    int stride = gridDim.x * blockDim.x;
    for (int i = blockIdx.x * blockDim.x + threadIdx.x; i < N_NODES * HC; i += stride) {
        g_x2[i] = gat_bias[i & (HC - 1)];
        if (i < N_NODES * HEADS) { g_amax[i] = -INFINITY; g_den[i] = 0.f; }
        if (i < NGRAPH * HC)     { g_mean[i] = 0.f; g_var[i] = 0.f; g_pool[i] = 0.f; }
        if (i < NGRAPH)          { g_cnt[i] = 0.f; g_gmax[i] = -INFINITY; g_gden[i] = 0.f; }
    }
}

// ---------------- xh = x @ lin_w^T  (lin_w: [HC, F_IN] row-major) ----------------
#define NODES_PER_BLK 8
__global__ void k_lin(const float* __restrict__ x, const float* __restrict__ lin_w) {
    extern __shared__ float smem[];
    float* ws = smem;                 // transposed [c][j], F_IN*HC floats
    float* xs = smem + F_IN * HC;     // [nn][c], NODES_PER_BLK*F_IN
    int tid = threadIdx.x;
    for (int t = tid; t < F_IN * HC; t += 256) {
        int j = t >> 6, c = t & 63;
        ws[c * HC + j] = lin_w[t];
    }
    int n0 = blockIdx.x * NODES_PER_BLK;
    for (int t = tid; t < NODES_PER_BLK * F_IN; t += 256) {
        int nn = t >> 6, c = t & 63;
        int n = n0 + nn;
        xs[t] = (n < N_NODES) ? x[n * F_IN + c] : 0.f;
    }
    __syncthreads();
    float acc[NODES_PER_BLK];
#pragma unroll
    for (int nn = 0; nn < NODES_PER_BLK; nn++) acc[nn] = 0.f;
    int j = tid;
#pragma unroll 8
    for (int c = 0; c < F_IN; c++) {
        float w = ws[c * HC + j];
#pragma unroll
        for (int nn = 0; nn < NODES_PER_BLK; nn++) acc[nn] += xs[nn * F_IN + c] * w;
    }
#pragma unroll
    for (int nn = 0; nn < NODES_PER_BLK; nn++) {
        int n = n0 + nn;
        if (n < N_NODES) g_xh[n * HC + j] = acc[nn];
    }
}

// ---------------- a_src / a_dst per (node, head) ----------------
__global__ void k_scores(const float* __restrict__ att_src, const float* __restrict__ att_dst) {
    int n = blockIdx.x;
    int j = threadIdx.x;
    float v = g_xh[n * HC + j];
    float ps = v * att_src[j];
    float pd = v * att_dst[j];
#pragma unroll
    for (int o = 16; o; o >>= 1) {
        ps += __shfl_down_sync(0xFFFFFFFFu, ps, o);
        pd += __shfl_down_sync(0xFFFFFFFFu, pd, o);
    }
    __shared__ float ss[8], sd[8];
    if ((j & 31) == 0) { ss[j >> 5] = ps; sd[j >> 5] = pd; }
    __syncthreads();
    if (j < HEADS) {
        g_asrc[n * HEADS + j] = ss[2 * j] + ss[2 * j + 1];
        g_adst[n * HEADS + j] = sd[2 * j] + sd[2 * j + 1];
    }
}

// ---------------- edge pass 1: raw leaky-relu score + segment max ----------------
__global__ void k_edge1(const int* __restrict__ ei, float* __restrict__ alpha) {
    int e = blockIdx.x * blockDim.x + threadIdx.x;
    if (e >= NTOT) return;
    int src, dst;
    if (e < N_EDGES) { src = ei[e]; dst = ei[N_EDGES + e]; }
    else             { src = dst = e - N_EDGES; }
#pragma unroll
    for (int h = 0; h < HEADS; h++) {
        float v = g_asrc[src * HEADS + h] + g_adst[dst * HEADS + h];
        float raw = (v > 0.f) ? v : 0.2f * v;
        alpha[e * HEADS + h] = raw;
        atomicMaxF(&g_amax[dst * HEADS + h], raw);
    }
}

// ---------------- edge pass 2: exp + segment sum ----------------
__global__ void k_edge2(const int* __restrict__ ei, float* __restrict__ alpha) {
    int e = blockIdx.x * blockDim.x + threadIdx.x;
    if (e >= NTOT) return;
    int dst = (e < N_EDGES) ? ei[N_EDGES + e] : (e - N_EDGES);
#pragma unroll
    for (int h = 0; h < HEADS; h++) {
        float ev = expf(alpha[e * HEADS + h] - g_amax[dst * HEADS + h]);
        alpha[e * HEADS + h] = ev;
        atomicAdd(&g_den[dst * HEADS + h], ev);
    }
}

// ---------------- edge pass 3: normalize alpha + scatter-aggregate messages ----------------
__global__ void k_edge3(const int* __restrict__ ei, float* __restrict__ alpha) {
    int e = blockIdx.x;
    int tid = threadIdx.x;
    int src, dst;
    if (e < N_EDGES) { src = ei[e]; dst = ei[N_EDGES + e]; }
    else             { src = dst = e - N_EDGES; }
    __shared__ float as[HEADS];
    if (tid < HEADS) {
        float a = alpha[e * HEADS + tid] / (g_den[dst * HEADS + tid] + 1e-16f);
        alpha[e * HEADS + tid] = a;
        as[tid] = a;
    }
    __syncthreads();
    atomicAdd(&g_x2[dst * HC + tid], g_xh[src * HC + tid] * as[tid >> 6]);
}

// ---------------- GraphNorm pass 1: per-graph sums + counts ----------------
__global__ void k_gnsum(const int* __restrict__ batch) {
    int n = blockIdx.x, j = threadIdx.x;
    int g = batch[n];
    if (j == 0) atomicAdd(&g_cnt[g], 1.f);
    atomicAdd(&g_mean[g * HC + j], g_x2[n * HC + j]);
}

__global__ void k_gnmeanfin() {
    int i = blockIdx.x * blockDim.x + threadIdx.x;
    if (i < NGRAPH * HC) g_mean[i] /= fmaxf(g_cnt[i >> 8], 1.f);
}

// ---------------- GraphNorm pass 2: center + var sums ----------------
__global__ void k_gnsubvar(const int* __restrict__ batch, const float* __restrict__ mscale) {
    int n = blockIdx.x, j = threadIdx.x;
    int g = batch[n];
    float sub = g_x2[n * HC + j] - g_mean[g * HC + j] * mscale[j];
    g_sub[n * HC + j] = sub;
    atomicAdd(&g_var[g * HC + j], sub * sub);
}

// ---------------- GraphNorm pass 3: normalize + relu ----------------
__global__ void k_gnapply(const int* __restrict__ batch, const float* __restrict__ w,
                          const float* __restrict__ b) {
    int n = blockIdx.x, j = threadIdx.x;
    int g = batch[n];
    float vv = g_var[g * HC + j] / fmaxf(g_cnt[g], 1.f);
    float hv = w[j] * g_sub[n * HC + j] * rsqrtf(vv + 1e-5f) + b[j];
    g_h[n * HC + j] = fmaxf(hv, 0.f);
}

// ---------------- gate MLP: sigmoid(relu(h@W1^T+b1)@W2^T+b2) + segment max ----------------
__global__ void k_gate(const int* __restrict__ batch,
                       const float* __restrict__ w1, const float* __restrict__ b1,
                       const float* __restrict__ w2, const float* __restrict__ b2) {
    __shared__ float ws[16 * HC];
    for (int t = threadIdx.x; t < 16 * HC; t += 256) ws[t] = w1[t];
    __syncthreads();
    int n = blockIdx.x * 256 + threadIdx.x;
    if (n >= N_NODES) return;
    float acc[16];
#pragma unroll
    for (int k = 0; k < 16; k++) acc[k] = b1[k];
    const float* hp = &g_h[n * HC];
    for (int c = 0; c < HC; c++) {
        float hv = hp[c];
#pragma unroll
        for (int k = 0; k < 16; k++) acc[k] += hv * ws[k * HC + c];
    }
    float z = b2[0];
#pragma unroll
    for (int k = 0; k < 16; k++) z += fmaxf(acc[k], 0.f) * w2[k];
    float gate = 1.f / (1.f + expf(-z));
    g_gate[n] = gate;
    atomicMaxF(&g_gmax[batch[n]], gate);
}

__global__ void k_gatenorm(const int* __restrict__ batch) {
    int n = blockIdx.x * blockDim.x + threadIdx.x;
    if (n >= N_NODES) return;
    int g = batch[n];
    float ev = expf(g_gate[n] - g_gmax[g]);
    g_gate[n] = ev;
    atomicAdd(&g_gden[g], ev);
}

__global__ void k_pool(const int* __restrict__ batch) {
    int n = blockIdx.x, j = threadIdx.x;
    int g = batch[n];
    float coeff = g_gate[n] / (g_gden[g] + 1e-16f);
    atomicAdd(&g_pool[g * HC + j], coeff * g_h[n * HC + j]);
}

// ---------------- head: relu(pool@fc1^T+b) @ out_w^T + out_b -> sigmoid ----------------
__global__ void k_head(const float* __restrict__ fc1_w, const float* __restrict__ fc1_b,
                       const float* __restrict__ out_w, const float* __restrict__ out_b,
                       float* __restrict__ out) {
    int g = blockIdx.x, o = threadIdx.x;  // 128 threads
    float acc = fc1_b[o];
    const float* p = &g_pool[g * HC];
    const float* w = &fc1_w[o * HC];
#pragma unroll 8
    for (int c = 0; c < HC; c++) acc += p[c] * w[c];
    acc = fmaxf(acc, 0.f) * out_w[o];
    __shared__ float red[ODIM];
    red[o] = acc;
    __syncthreads();
#pragma unroll
    for (int s = 64; s; s >>= 1) {
        if (o < s) red[o] += red[o + s];
        __syncthreads();
    }
    if (o == 0) out[g] = 1.f / (1.f + expf(-(red[0] + out_b[0])));
}

// ---------------- launch ----------------
extern "C" void kernel_launch(void* const* d_in, const int* in_sizes, int n_in,
                              void* d_out, int out_size) {
    const float* x        = (const float*)d_in[0];
    const int*   ei       = (const int*)  d_in[1];
    const int*   batch    = (const int*)  d_in[2];
    const float* lin_w    = (const float*)d_in[3];
    const float* att_src  = (const float*)d_in[4];
    const float* att_dst  = (const float*)d_in[5];
    const float* gat_bias = (const float*)d_in[6];
    const float* gn_w     = (const float*)d_in[7];
    const float* gn_b     = (const float*)d_in[8];
    const float* gn_ms    = (const float*)d_in[9];
    const float* fc1_w    = (const float*)d_in[10];
    const float* fc1_b    = (const float*)d_in[11];
    const float* out_w    = (const float*)d_in[12];
    const float* out_b    = (const float*)d_in[13];
    const float* att1_w   = (const float*)d_in[14];
    const float* att1_b   = (const float*)d_in[15];
    const float* att2_w   = (const float*)d_in[16];
    const float* att2_b   = (const float*)d_in[17];

    float* out   = (float*)d_out;
    float* alpha = out + NGRAPH;   // [NTOT, HEADS]

    int linSmem = (F_IN * HC + NODES_PER_BLK * F_IN) * (int)sizeof(float);
    cudaFuncSetAttribute(k_lin, cudaFuncAttributeMaxDynamicSharedMemorySize, linSmem);

    k_init<<<12500, 1024>>>(gat_bias);
    k_lin<<<(N_NODES + NODES_PER_BLK - 1) / NODES_PER_BLK, 256, linSmem>>>(x, lin_w);
    k_scores<<<N_NODES, 256>>>(att_src, att_dst);
    k_edge1<<<(NTOT + 255) / 256, 256>>>(ei, alpha);
    k_edge2<<<(NTOT + 255) / 256, 256>>>(ei, alpha);
    k_edge3<<<NTOT, 256>>>(ei, alpha);
    k_gnsum<<<N_NODES, 256>>>(batch);
    k_gnmeanfin<<<(NGRAPH * HC + 255) / 256, 256>>>();
    k_gnsubvar<<<N_NODES, 256>>>(batch, gn_ms);
    k_gnapply<<<N_NODES, 256>>>(batch, gn_w, gn_b);
    k_gate<<<(N_NODES + 255) / 256, 256>>>(batch, att1_w, att1_b, att2_w, att2_b);
    k_gatenorm<<<(N_NODES + 255) / 256, 256>>>(batch);
    k_pool<<<N_NODES, 256>>>(batch);
    k_head<<<NGRAPH, ODIM>>>(fc1_w, fc1_b, out_w, out_b, out);
}

// round 2
// speedup vs baseline: 2.6929x; 2.6929x over previous
#include <cuda_runtime.h>
#include <math.h>

#define N_NODES 50000
#define N_EDGES 800000
#define NTOT    850000   // E + N self loops
#define NGRAPH  256
#define F_IN    64
#define HEADS   4
#define HC      256      // HEADS*F_IN
#define ODIM    128

// ---------------- scratch (device globals; no allocation) ----------------
__device__ float g_xh  [N_NODES * HC];    // x @ lin_w^T
__device__ float g_asrc[N_NODES * HEADS];
__device__ float g_adst[N_NODES * HEADS];
__device__ float g_x2  [N_NODES * HC];    // GAT output
__device__ float g_h   [N_NODES * HC];    // after norm + relu
__device__ float g_gate[N_NODES];
__device__ float g_pool[NGRAPH * HC];
__device__ int   g_deg [N_NODES];
__device__ int   g_rowptr[N_NODES + 1];
__device__ int   g_woff[N_NODES];
__device__ int   g_csr [NTOT];
__device__ int   g_gs  [NGRAPH];          // graph node range start
__device__ int   g_ge  [NGRAPH];          // graph node range end

// ---------------- init ----------------
__global__ void k_init() {
    int i = blockIdx.x * blockDim.x + threadIdx.x;
    if (i < N_NODES) g_deg[i] = 0;
    if (i < NGRAPH) { g_gs[i] = N_NODES; g_ge[i] = 0; }
}

// ---------------- xh = x @ lin_w^T  (lin_w: [HC, F_IN] row-major) ----------------
#define NODES_PER_BLK 32
__global__ void k_lin(const float* __restrict__ x, const float* __restrict__ lin_w) {
    extern __shared__ float smem[];
    float* ws = smem;                 // transposed [c][j], F_IN*HC floats
    float* xs = smem + F_IN * HC;     // [nn][c], NODES_PER_BLK*F_IN
    int tid = threadIdx.x;
    for (int t = tid; t < F_IN * HC; t += 256) {
        int j = t >> 6, c = t & 63;
        ws[c * HC + j] = lin_w[t];
    }
    int n0 = blockIdx.x * NODES_PER_BLK;
    for (int t = tid; t < NODES_PER_BLK * F_IN; t += 256) {
        int nn = t >> 6, c = t & 63;
        int n = n0 + nn;
        xs[t] = (n < N_NODES) ? x[n * F_IN + c] : 0.f;
    }
    __syncthreads();
    float acc[NODES_PER_BLK];
#pragma unroll
    for (int nn = 0; nn < NODES_PER_BLK; nn++) acc[nn] = 0.f;
    int j = tid;
#pragma unroll 4
    for (int c = 0; c < F_IN; c++) {
        float w = ws[c * HC + j];
#pragma unroll
        for (int nn = 0; nn < NODES_PER_BLK; nn++) acc[nn] += xs[nn * F_IN + c] * w;
    }
#pragma unroll
    for (int nn = 0; nn < NODES_PER_BLK; nn++) {
        int n = n0 + nn;
        if (n < N_NODES) g_xh[n * HC + j] = acc[nn];
    }
}

// ---------------- a_src / a_dst per (node, head) ----------------
__global__ void k_scores(const float* __restrict__ att_src, const float* __restrict__ att_dst) {
    int n = blockIdx.x;
    int j = threadIdx.x;
    float v = g_xh[n * HC + j];
    float ps = v * att_src[j];
    float pd = v * att_dst[j];
#pragma unroll
    for (int o = 16; o; o >>= 1) {
        ps += __shfl_down_sync(0xFFFFFFFFu, ps, o);
        pd += __shfl_down_sync(0xFFFFFFFFu, pd, o);
    }
    __shared__ float ss[8], sd[8];
    if ((j & 31) == 0) { ss[j >> 5] = ps; sd[j >> 5] = pd; }
    __syncthreads();
    if (j < HEADS) {
        g_asrc[n * HEADS + j] = ss[2 * j] + ss[2 * j + 1];
        g_adst[n * HEADS + j] = sd[2 * j] + sd[2 * j + 1];
    }
}

// ---------------- CSR build ----------------
__global__ void k_hist(const int* __restrict__ ei) {
    int e = blockIdx.x * blockDim.x + threadIdx.x;
    if (e >= NTOT) return;
    int dst = (e < N_EDGES) ? ei[N_EDGES + e] : (e - N_EDGES);
    atomicAdd(&g_deg[dst], 1);
}

__global__ void k_scan() {   // single block, 1024 threads
    __shared__ int sm[1024];
    const int CH = (N_NODES + 1023) / 1024;  // 49
    int t = threadIdx.x;
    int base = t * CH;
    int s = 0;
    for (int i = 0; i < CH; i++) { int idx = base + i; if (idx < N_NODES) s += g_deg[idx]; }
    sm[t] = s;
    __syncthreads();
    for (int o = 1; o < 1024; o <<= 1) {
        int v = (t >= o) ? sm[t - o] : 0;
        __syncthreads();
        sm[t] += v;
        __syncthreads();
    }
    int off = (t == 0) ? 0 : sm[t - 1];
    for (int i = 0; i < CH; i++) {
        int idx = base + i;
        if (idx < N_NODES) { g_rowptr[idx] = off; g_woff[idx] = off; off += g_deg[idx]; }
    }
    if (t == 0) g_rowptr[N_NODES] = NTOT;
}

__global__ void k_fill(const int* __restrict__ ei) {
    int e = blockIdx.x * blockDim.x + threadIdx.x;
    if (e >= NTOT) return;
    int dst = (e < N_EDGES) ? ei[N_EDGES + e] : (e - N_EDGES);
    int pos = atomicAdd(&g_woff[dst], 1);
    g_csr[pos] = e;
}

// ---------------- graph node ranges (batch is sorted) ----------------
__global__ void k_bounds(const int* __restrict__ batch) {
    int n = blockIdx.x * blockDim.x + threadIdx.x;
    if (n >= N_NODES) return;
    int g = batch[n];
    atomicMin(&g_gs[g], n);
    atomicMax(&g_ge[g], n + 1);
}

// ---------------- fused GAT: warp per dst node ----------------
__global__ void k_gat(const int* __restrict__ ei, float* __restrict__ alpha,
                      const float* __restrict__ gat_bias) {
    int warp = threadIdx.x >> 5;
    int lane = threadIdx.x & 31;
    int n = blockIdx.x * 8 + warp;
    if (n >= N_NODES) return;
    int start = g_rowptr[n], end = g_rowptr[n + 1];

    float ad[4];
    *(float4*)ad = *(const float4*)&g_adst[n * HEADS];

    // phase 1: per-head max of leaky-relu scores
    float m0 = -INFINITY, m1 = -INFINITY, m2 = -INFINITY, m3 = -INFINITY;
    for (int i = start + lane; i < end; i += 32) {
        int e = g_csr[i];
        int src = (e < N_EDGES) ? ei[e] : (e - N_EDGES);
        float as[4];
        *(float4*)as = *(const float4*)&g_asrc[src * HEADS];
        float v, r;
        v = as[0] + ad[0]; r = (v > 0.f) ? v : 0.2f * v; m0 = fmaxf(m0, r);
        v = as[1] + ad[1]; r = (v > 0.f) ? v : 0.2f * v; m1 = fmaxf(m1, r);
        v = as[2] + ad[2]; r = (v > 0.f) ? v : 0.2f * v; m2 = fmaxf(m2, r);
        v = as[3] + ad[3]; r = (v > 0.f) ? v : 0.2f * v; m3 = fmaxf(m3, r);
    }
#pragma unroll
    for (int o = 16; o; o >>= 1) {
        m0 = fmaxf(m0, __shfl_xor_sync(0xFFFFFFFFu, m0, o));
        m1 = fmaxf(m1, __shfl_xor_sync(0xFFFFFFFFu, m1, o));
        m2 = fmaxf(m2, __shfl_xor_sync(0xFFFFFFFFu, m2, o));
        m3 = fmaxf(m3, __shfl_xor_sync(0xFFFFFFFFu, m3, o));
    }

    // phase 2: exp + sum; store exp to alpha
    float s0 = 0.f, s1 = 0.f, s2 = 0.f, s3 = 0.f;
    for (int i = start + lane; i < end; i += 32) {
        int e = g_csr[i];
        int src = (e < N_EDGES) ? ei[e] : (e - N_EDGES);
        float as[4];
        *(float4*)as = *(const float4*)&g_asrc[src * HEADS];
        float v, r, ev;
        float4 av;
        v = as[0] + ad[0]; r = (v > 0.f) ? v : 0.2f * v; ev = __expf(r - m0); s0 += ev; av.x = ev;
        v = as[1] + ad[1]; r = (v > 0.f) ? v : 0.2f * v; ev = __expf(r - m1); s1 += ev; av.y = ev;
        v = as[2] + ad[2]; r = (v > 0.f) ? v : 0.2f * v; ev = __expf(r - m2); s2 += ev; av.z = ev;
        v = as[3] + ad[3]; r = (v > 0.f) ? v : 0.2f * v; ev = __expf(r - m3); s3 += ev; av.w = ev;
        *(float4*)&alpha[e * HEADS] = av;
    }
#pragma unroll
    for (int o = 16; o; o >>= 1) {
        s0 += __shfl_xor_sync(0xFFFFFFFFu, s0, o);
        s1 += __shfl_xor_sync(0xFFFFFFFFu, s1, o);
        s2 += __shfl_xor_sync(0xFFFFFFFFu, s2, o);
        s3 += __shfl_xor_sync(0xFFFFFFFFu, s3, o);
    }
    float i0 = 1.f / (s0 + 1e-16f);
    float i1 = 1.f / (s1 + 1e-16f);
    float i2 = 1.f / (s2 + 1e-16f);
    float i3 = 1.f / (s3 + 1e-16f);

    // phase 2.5: normalize alpha in place
    for (int i = start + lane; i < end; i += 32) {
        int e = g_csr[i];
        float4 av = *(float4*)&alpha[e * HEADS];
        av.x *= i0; av.y *= i1; av.z *= i2; av.w *= i3;
        *(float4*)&alpha[e * HEADS] = av;
    }
    __threadfence_block();
    __syncwarp();

    // phase 3: aggregate. lane owns channels [lane*8, lane*8+8); head = lane>>3
    int h = lane >> 3;
    float4 acc0 = {0.f, 0.f, 0.f, 0.f}, acc1 = {0.f, 0.f, 0.f, 0.f};
    for (int i = start; i < end; i++) {
        int e = g_csr[i];
        int src = (e < N_EDGES) ? ei[e] : (e - N_EDGES);
        float a = alpha[e * HEADS + h];
        const float4* xp = (const float4*)&g_xh[src * HC + lane * 8];
        float4 v0 = xp[0], v1 = xp[1];
        acc0.x += a * v0.x; acc0.y += a * v0.y; acc0.z += a * v0.z; acc0.w += a * v0.w;
        acc1.x += a * v1.x; acc1.y += a * v1.y; acc1.z += a * v1.z; acc1.w += a * v1.w;
    }
    const float4* bp = (const float4*)&gat_bias[lane * 8];
    float4 b0 = bp[0], b1 = bp[1];
    acc0.x += b0.x; acc0.y += b0.y; acc0.z += b0.z; acc0.w += b0.w;
    acc1.x += b1.x; acc1.y += b1.y; acc1.z += b1.z; acc1.w += b1.w;
    float4* op = (float4*)&g_x2[n * HC + lane * 8];
    op[0] = acc0; op[1] = acc1;
}

// ---------------- fused GraphNorm + ReLU: block per graph ----------------
__global__ void k_gn(const float* __restrict__ mscale, const float* __restrict__ w,
                     const float* __restrict__ b) {
    int g = blockIdx.x, j = threadIdx.x;
    int s = g_gs[g], e = g_ge[g];
    float cnt = fmaxf((float)(e - s), 1.f);
    float inv_cnt = 1.f / cnt;
    float mean = 0.f;
    for (int n = s; n < e; n++) mean += g_x2[n * HC + j];
    mean *= inv_cnt;
    float msj = mscale[j];
    float mm = mean * msj;
    float var = 0.f;
    for (int n = s; n < e; n++) { float sub = g_x2[n * HC + j] - mm; var += sub * sub; }
    var *= inv_cnt;
    float sc = w[j] * rsqrtf(var + 1e-5f);
    float bj = b[j];
    for (int n = s; n < e; n++) {
        float hv = sc * (g_x2[n * HC + j] - mm) + bj;
        g_h[n * HC + j] = fmaxf(hv, 0.f);
    }
}

// ---------------- gate MLP: sigmoid(relu(h@W1^T+b1)@W2^T+b2) ----------------
__global__ void k_gate(const float* __restrict__ w1, const float* __restrict__ b1,
                       const float* __restrict__ w2, const float* __restrict__ b2) {
    __shared__ float ws[16 * HC];
    for (int t = threadIdx.x; t < 16 * HC; t += 256) ws[t] = w1[t];
    __syncthreads();
    int n = blockIdx.x * 256 + threadIdx.x;
    if (n >= N_NODES) return;
    float acc[16];
#pragma unroll
    for (int k = 0; k < 16; k++) acc[k] = b1[k];
    const float* hp = &g_h[n * HC];
    for (int c = 0; c < HC; c++) {
        float hv = hp[c];
#pragma unroll
        for (int k = 0; k < 16; k++) acc[k] += hv * ws[k * HC + c];
    }
    float z = b2[0];
#pragma unroll
    for (int k = 0; k < 16; k++) z += fmaxf(acc[k], 0.f) * w2[k];
    g_gate[n] = 1.f / (1.f + __expf(-z));
}

// ---------------- fused softmax pool: block per graph ----------------
__global__ void k_poolg() {
    int g = blockIdx.x, tid = threadIdx.x;
    int s = g_gs[g], e = g_ge[g];
    __shared__ float red[256];
    __shared__ float wts[512];

    float m = -INFINITY;
    for (int n = s + tid; n < e; n += 256) m = fmaxf(m, g_gate[n]);
    red[tid] = m; __syncthreads();
#pragma unroll
    for (int o = 128; o; o >>= 1) { if (tid < o) red[tid] = fmaxf(red[tid], red[tid + o]); __syncthreads(); }
    m = red[0]; __syncthreads();

    float sum = 0.f;
    for (int n = s + tid; n < e; n += 256) sum += __expf(g_gate[n] - m);
    red[tid] = sum; __syncthreads();
#pragma unroll
    for (int o = 128; o; o >>= 1) { if (tid < o) red[tid] += red[tid + o]; __syncthreads(); }
    float inv = 1.f / (red[0] + 1e-16f);
    __syncthreads();

    float acc = 0.f;
    for (int chunk = s; chunk < e; chunk += 512) {
        int cn = min(512, e - chunk);
        for (int i = tid; i < cn; i += 256) wts[i] = __expf(g_gate[chunk + i] - m) * inv;
        __syncthreads();
        for (int i = 0; i < cn; i++) acc += wts[i] * g_h[(chunk + i) * HC + tid];
        __syncthreads();
    }
    g_pool[g * HC + tid] = acc;
}

// ---------------- head: relu(pool@fc1^T+b) @ out_w^T + out_b -> sigmoid ----------------
__global__ void k_head(const float* __restrict__ fc1_w, const float* __restrict__ fc1_b,
                       const float* __restrict__ out_w, const float* __restrict__ out_b,
                       float* __restrict__ out) {
    int g = blockIdx.x, o = threadIdx.x;  // 128 threads
    float acc = fc1_b[o];
    const float* p = &g_pool[g * HC];
    const float* w = &fc1_w[o * HC];
#pragma unroll 8
    for (int c = 0; c < HC; c++) acc += p[c] * w[c];
    acc = fmaxf(acc, 0.f) * out_w[o];
    __shared__ float red[ODIM];
    red[o] = acc;
    __syncthreads();
#pragma unroll
    for (int s = 64; s; s >>= 1) {
        if (o < s) red[o] += red[o + s];
        __syncthreads();
    }
    if (o == 0) out[g] = 1.f / (1.f + __expf(-(red[0] + out_b[0])));
}

// ---------------- launch ----------------
extern "C" void kernel_launch(void* const* d_in, const int* in_sizes, int n_in,
                              void* d_out, int out_size) {
    const float* x        = (const float*)d_in[0];
    const int*   ei       = (const int*)  d_in[1];
    const int*   batch    = (const int*)  d_in[2];
    const float* lin_w    = (const float*)d_in[3];
    const float* att_src  = (const float*)d_in[4];
    const float* att_dst  = (const float*)d_in[5];
    const float* gat_bias = (const float*)d_in[6];
    const float* gn_w     = (const float*)d_in[7];
    const float* gn_b     = (const float*)d_in[8];
    const float* gn_ms    = (const float*)d_in[9];
    const float* fc1_w    = (const float*)d_in[10];
    const float* fc1_b    = (const float*)d_in[11];
    const float* out_w    = (const float*)d_in[12];
    const float* out_b    = (const float*)d_in[13];
    const float* att1_w   = (const float*)d_in[14];
    const float* att1_b   = (const float*)d_in[15];
    const float* att2_w   = (const float*)d_in[16];
    const float* att2_b   = (const float*)d_in[17];

    float* out   = (float*)d_out;
    float* alpha = out + NGRAPH;   // [NTOT, HEADS]

    int linSmem = (F_IN * HC + NODES_PER_BLK * F_IN) * (int)sizeof(float);
    cudaFuncSetAttribute(k_lin, cudaFuncAttributeMaxDynamicSharedMemorySize, linSmem);

    k_init<<<(N_NODES + 255) / 256, 256>>>();
    k_lin<<<(N_NODES + NODES_PER_BLK - 1) / NODES_PER_BLK, 256, linSmem>>>(x, lin_w);
    k_scores<<<N_NODES, 256>>>(att_src, att_dst);
    k_hist<<<(NTOT + 255) / 256, 256>>>(ei);
    k_scan<<<1, 1024>>>();
    k_fill<<<(NTOT + 255) / 256, 256>>>(ei);
    k_bounds<<<(N_NODES + 255) / 256, 256>>>(batch);
    k_gat<<<(N_NODES + 7) / 8, 256>>>(ei, alpha, gat_bias);
    k_gn<<<NGRAPH, 256>>>(gn_ms, gn_w, gn_b);
    k_gate<<<(N_NODES + 255) / 256, 256>>>(att1_w, att1_b, att2_w, att2_b);
    k_poolg<<<NGRAPH, 256>>>();
    k_head<<<NGRAPH, ODIM>>>(fc1_w, fc1_b, out_w, out_b, out);
}

// round 3
// speedup vs baseline: 3.6703x; 1.3629x over previous
#include <cuda_runtime.h>
#include <math.h>

#define N_NODES 50000
#define N_EDGES 800000
#define NTOT    850000   // E + N self loops
#define NGRAPH  256
#define F_IN    64
#define HEADS   4
#define HC      256      // HEADS*F_IN
#define ODIM    128

// ---------------- scratch (device globals; no allocation) ----------------
__device__ float g_xh  [N_NODES * HC];    // x @ lin_w^T
__device__ float g_asrc[N_NODES * HEADS];
__device__ float g_adst[N_NODES * HEADS];
__device__ float g_x2  [N_NODES * HC];    // GAT output
__device__ float g_h   [N_NODES * HC];    // after norm + relu
__device__ float g_gate[N_NODES];
__device__ float g_pool[NGRAPH * HC];
__device__ float g_mean[NGRAPH * HC];     // sum -> coefA
__device__ float g_var [NGRAPH * HC];     // sumsq -> coefB
__device__ int   g_deg [N_NODES];
__device__ int   g_rowptr[N_NODES + 1];
__device__ int   g_woff[N_NODES];
__device__ int   g_csr [NTOT];
__device__ int   g_gs  [NGRAPH];
__device__ int   g_ge  [NGRAPH];

// ---------------- init ----------------
__global__ void k_init() {
    int i = blockIdx.x * blockDim.x + threadIdx.x;
    if (i < N_NODES) g_deg[i] = 0;
    if (i < NGRAPH * HC) { g_mean[i] = 0.f; g_var[i] = 0.f; g_pool[i] = 0.f; }
    if (i < NGRAPH) { g_gs[i] = N_NODES; g_ge[i] = 0; }
}

// ---------------- xh = x @ lin_w^T + fused attention scores ----------------
#define LIN_NPB 64
__global__ __launch_bounds__(256) void k_lin(const float* __restrict__ x,
                                             const float* __restrict__ lin_w,
                                             const float* __restrict__ att_src,
                                             const float* __restrict__ att_dst) {
    __shared__ __align__(16) float xs[LIN_NPB * F_IN];   // 16KB
    __shared__ float sps[LIN_NPB][8];
    __shared__ float spd[LIN_NPB][8];
    int j = threadIdx.x;          // output channel
    int lane = j & 31, warp = j >> 5;

    float wreg[F_IN];
#pragma unroll
    for (int c = 0; c < F_IN; c++) wreg[c] = lin_w[j * F_IN + c];
    float asj = att_src[j], adj = att_dst[j];

    int n0 = blockIdx.x * LIN_NPB;
    for (int t = j; t < LIN_NPB * F_IN; t += 256) {
        int gi = n0 * F_IN + t;
        xs[t] = (gi < N_NODES * F_IN) ? x[gi] : 0.f;
    }
    __syncthreads();

    for (int nn = 0; nn < LIN_NPB; nn++) {
        const float4* xp = (const float4*)&xs[nn * F_IN];
        float acc = 0.f;
#pragma unroll
        for (int c4 = 0; c4 < F_IN / 4; c4++) {
            float4 v = xp[c4];
            acc += v.x * wreg[4 * c4] + v.y * wreg[4 * c4 + 1]
                 + v.z * wreg[4 * c4 + 2] + v.w * wreg[4 * c4 + 3];
        }
        int n = n0 + nn;
        if (n < N_NODES) g_xh[n * HC + j] = acc;
        float ps = acc * asj, pd = acc * adj;
#pragma unroll
        for (int o = 16; o; o >>= 1) {
            ps += __shfl_xor_sync(0xFFFFFFFFu, ps, o);
            pd += __shfl_xor_sync(0xFFFFFFFFu, pd, o);
        }
        if (lane == 0) { sps[nn][warp] = ps; spd[nn][warp] = pd; }
    }
    __syncthreads();
    // 256 threads -> 64 nodes x 4 heads
    int nn = j >> 2, h = j & 3;
    int n = n0 + nn;
    if (n < N_NODES) {
        g_asrc[n * HEADS + h] = sps[nn][2 * h] + sps[nn][2 * h + 1];
        g_adst[n * HEADS + h] = spd[nn][2 * h] + spd[nn][2 * h + 1];
    }
}

// ---------------- CSR build ----------------
__global__ void k_hist(const int* __restrict__ ei) {
    int e = blockIdx.x * blockDim.x + threadIdx.x;
    if (e >= NTOT) return;
    int dst = (e < N_EDGES) ? ei[N_EDGES + e] : (e - N_EDGES);
    atomicAdd(&g_deg[dst], 1);
}

__global__ void k_scan() {   // single block, 1024 threads
    __shared__ int sm[1024];
    const int CH = (N_NODES + 1023) / 1024;
    int t = threadIdx.x;
    int base = t * CH;
    int s = 0;
    for (int i = 0; i < CH; i++) { int idx = base + i; if (idx < N_NODES) s += g_deg[idx]; }
    sm[t] = s;
    __syncthreads();
    for (int o = 1; o < 1024; o <<= 1) {
        int v = (t >= o) ? sm[t - o] : 0;
        __syncthreads();
        sm[t] += v;
        __syncthreads();
    }
    int off = (t == 0) ? 0 : sm[t - 1];
    for (int i = 0; i < CH; i++) {
        int idx = base + i;
        if (idx < N_NODES) { g_rowptr[idx] = off; g_woff[idx] = off; off += g_deg[idx]; }
    }
    if (t == 0) g_rowptr[N_NODES] = NTOT;
}

__global__ void k_fill(const int* __restrict__ ei) {
    int e = blockIdx.x * blockDim.x + threadIdx.x;
    if (e >= NTOT) return;
    int dst = (e < N_EDGES) ? ei[N_EDGES + e] : (e - N_EDGES);
    int pos = atomicAdd(&g_woff[dst], 1);
    g_csr[pos] = e;
}

__global__ void k_bounds(const int* __restrict__ batch) {
    int n = blockIdx.x * blockDim.x + threadIdx.x;
    if (n >= N_NODES) return;
    int g = batch[n];
    atomicMin(&g_gs[g], n);
    atomicMax(&g_ge[g], n + 1);
}

// ---------------- fused GAT: warp per dst node, smem edge cache ----------------
#define GAT_WARPS 8
#define GAT_CAP   128
__global__ __launch_bounds__(256) void k_gat(const int* __restrict__ ei,
                                             float* __restrict__ alpha,
                                             const float* __restrict__ gat_bias) {
    __shared__ int   s_e  [GAT_WARPS][GAT_CAP];
    __shared__ int   s_src[GAT_WARPS][GAT_CAP];
    __shared__ __align__(16) float s_al[GAT_WARPS][GAT_CAP * 4];
    int warp = threadIdx.x >> 5;
    int lane = threadIdx.x & 31;
    int n = blockIdx.x * GAT_WARPS + warp;
    if (n >= N_NODES) return;
    int start = g_rowptr[n], end = g_rowptr[n + 1];
    int d = end - start;

    float ad[4];
    *(float4*)ad = *(const float4*)&g_adst[n * HEADS];

    float m0 = -INFINITY, m1 = -INFINITY, m2 = -INFINITY, m3 = -INFINITY;
    float s0 = 0.f, s1 = 0.f, s2 = 0.f, s3 = 0.f;

    if (d <= GAT_CAP) {
        // phase A: gather, compute raw leaky scores into smem, track max
        for (int li = lane; li < d; li += 32) {
            int e = g_csr[start + li];
            int src = (e < N_EDGES) ? ei[e] : (e - N_EDGES);
            s_e[warp][li] = e; s_src[warp][li] = src;
            float as[4];
            *(float4*)as = *(const float4*)&g_asrc[src * HEADS];
            float4 rv;
            float v;
            v = as[0] + ad[0]; rv.x = (v > 0.f) ? v : 0.2f * v; m0 = fmaxf(m0, rv.x);
            v = as[1] + ad[1]; rv.y = (v > 0.f) ? v : 0.2f * v; m1 = fmaxf(m1, rv.y);
            v = as[2] + ad[2]; rv.z = (v > 0.f) ? v : 0.2f * v; m2 = fmaxf(m2, rv.z);
            v = as[3] + ad[3]; rv.w = (v > 0.f) ? v : 0.2f * v; m3 = fmaxf(m3, rv.w);
            *(float4*)&s_al[warp][li * 4] = rv;
        }
#pragma unroll
        for (int o = 16; o; o >>= 1) {
            m0 = fmaxf(m0, __shfl_xor_sync(0xFFFFFFFFu, m0, o));
            m1 = fmaxf(m1, __shfl_xor_sync(0xFFFFFFFFu, m1, o));
            m2 = fmaxf(m2, __shfl_xor_sync(0xFFFFFFFFu, m2, o));
            m3 = fmaxf(m3, __shfl_xor_sync(0xFFFFFFFFu, m3, o));
        }
        __syncwarp();
        // phase B: exp + sum (smem only)
        for (int li = lane; li < d; li += 32) {
            float4 rv = *(float4*)&s_al[warp][li * 4];
            rv.x = __expf(rv.x - m0); s0 += rv.x;
            rv.y = __expf(rv.y - m1); s1 += rv.y;
            rv.z = __expf(rv.z - m2); s2 += rv.z;
            rv.w = __expf(rv.w - m3); s3 += rv.w;
            *(float4*)&s_al[warp][li * 4] = rv;
        }
#pragma unroll
        for (int o = 16; o; o >>= 1) {
            s0 += __shfl_xor_sync(0xFFFFFFFFu, s0, o);
            s1 += __shfl_xor_sync(0xFFFFFFFFu, s1, o);
            s2 += __shfl_xor_sync(0xFFFFFFFFu, s2, o);
            s3 += __shfl_xor_sync(0xFFFFFFFFu, s3, o);
        }
        float i0 = 1.f / (s0 + 1e-16f), i1 = 1.f / (s1 + 1e-16f);
        float i2 = 1.f / (s2 + 1e-16f), i3 = 1.f / (s3 + 1e-16f);
        __syncwarp();
        // phase C: normalize in smem + single gmem alpha write
        for (int li = lane; li < d; li += 32) {
            float4 av = *(float4*)&s_al[warp][li * 4];
            av.x *= i0; av.y *= i1; av.z *= i2; av.w *= i3;
            *(float4*)&s_al[warp][li * 4] = av;
            *(float4*)&alpha[s_e[warp][li] * 4] = av;
        }
        __syncwarp();
        // phase D: aggregate; lane owns 8 channels, head = lane>>3
        int h = lane >> 3;
        float4 acc0 = {0.f,0.f,0.f,0.f}, acc1 = {0.f,0.f,0.f,0.f};
        for (int li = 0; li < d; li++) {
            int src = s_src[warp][li];
            float a = s_al[warp][li * 4 + h];
            const float4* xp = (const float4*)&g_xh[src * HC + lane * 8];
            float4 v0 = xp[0], v1 = xp[1];
            acc0.x += a * v0.x; acc0.y += a * v0.y; acc0.z += a * v0.z; acc0.w += a * v0.w;
            acc1.x += a * v1.x; acc1.y += a * v1.y; acc1.z += a * v1.z; acc1.w += a * v1.w;
        }
        const float4* bp = (const float4*)&gat_bias[lane * 8];
        float4 b0 = bp[0], b1 = bp[1];
        acc0.x += b0.x; acc0.y += b0.y; acc0.z += b0.z; acc0.w += b0.w;
        acc1.x += b1.x; acc1.y += b1.y; acc1.z += b1.z; acc1.w += b1.w;
        float4* op = (float4*)&g_x2[n * HC + lane * 8];
        op[0] = acc0; op[1] = acc1;
    } else {
        // fallback: gmem 3-pass (rare/never for this data)
        for (int i = start + lane; i < end; i += 32) {
            int e = g_csr[i];
            int src = (e < N_EDGES) ? ei[e] : (e - N_EDGES);
            float as[4];
            *(float4*)as = *(const float4*)&g_asrc[src * HEADS];
            float v, r;
            v = as[0] + ad[0]; r = (v > 0.f) ? v : 0.2f * v; m0 = fmaxf(m0, r);
            v = as[1] + ad[1]; r = (v > 0.f) ? v : 0.2f * v; m1 = fmaxf(m1, r);
            v = as[2] + ad[2]; r = (v > 0.f) ? v : 0.2f * v; m2 = fmaxf(m2, r);
            v = as[3] + ad[3]; r = (v > 0.f) ? v : 0.2f * v; m3 = fmaxf(m3, r);
        }
#pragma unroll
        for (int o = 16; o; o >>= 1) {
            m0 = fmaxf(m0, __shfl_xor_sync(0xFFFFFFFFu, m0, o));
            m1 = fmaxf(m1, __shfl_xor_sync(0xFFFFFFFFu, m1, o));
            m2 = fmaxf(m2, __shfl_xor_sync(0xFFFFFFFFu, m2, o));
            m3 = fmaxf(m3, __shfl_xor_sync(0xFFFFFFFFu, m3, o));
        }
        for (int i = start + lane; i < end; i += 32) {
            int e = g_csr[i];
            int src = (e < N_EDGES) ? ei[e] : (e - N_EDGES);
            float as[4];
            *(float4*)as = *(const float4*)&g_asrc[src * HEADS];
            float v, r; float4 av;
            v = as[0] + ad[0]; r = (v > 0.f) ? v : 0.2f * v; av.x = __expf(r - m0); s0 += av.x;
            v = as[1] + ad[1]; r = (v > 0.f) ? v : 0.2f * v; av.y = __expf(r - m1); s1 += av.y;
            v = as[2] + ad[2]; r = (v > 0.f) ? v : 0.2f * v; av.z = __expf(r - m2); s2 += av.z;
            v = as[3] + ad[3]; r = (v > 0.f) ? v : 0.2f * v; av.w = __expf(r - m3); s3 += av.w;
            *(float4*)&alpha[e * 4] = av;
        }
#pragma unroll
        for (int o = 16; o; o >>= 1) {
            s0 += __shfl_xor_sync(0xFFFFFFFFu, s0, o);
            s1 += __shfl_xor_sync(0xFFFFFFFFu, s1, o);
            s2 += __shfl_xor_sync(0xFFFFFFFFu, s2, o);
            s3 += __shfl_xor_sync(0xFFFFFFFFu, s3, o);
        }
        float i0 = 1.f / (s0 + 1e-16f), i1 = 1.f / (s1 + 1e-16f);
        float i2 = 1.f / (s2 + 1e-16f), i3 = 1.f / (s3 + 1e-16f);
        for (int i = start + lane; i < end; i += 32) {
            int e = g_csr[i];
            float4 av = *(float4*)&alpha[e * 4];
            av.x *= i0; av.y *= i1; av.z *= i2; av.w *= i3;
            *(float4*)&alpha[e * 4] = av;
        }
        __threadfence_block();
        __syncwarp();
        int h = lane >> 3;
        float4 acc0 = {0.f,0.f,0.f,0.f}, acc1 = {0.f,0.f,0.f,0.f};
        for (int i = start; i < end; i++) {
            int e = g_csr[i];
            int src = (e < N_EDGES) ? ei[e] : (e - N_EDGES);
            float a = alpha[e * 4 + h];
            const float4* xp = (const float4*)&g_xh[src * HC + lane * 8];
            float4 v0 = xp[0], v1 = xp[1];
            acc0.x += a * v0.x; acc0.y += a * v0.y; acc0.z += a * v0.z; acc0.w += a * v0.w;
            acc1.x += a * v1.x; acc1.y += a * v1.y; acc1.z += a * v1.z; acc1.w += a * v1.w;
        }
        const float4* bp = (const float4*)&gat_bias[lane * 8];
        float4 b0 = bp[0], b1 = bp[1];
        acc0.x += b0.x; acc0.y += b0.y; acc0.z += b0.z; acc0.w += b0.w;
        acc1.x += b1.x; acc1.y += b1.y; acc1.z += b1.z; acc1.w += b1.w;
        float4* op = (float4*)&g_x2[n * HC + lane * 8];
        op[0] = acc0; op[1] = acc1;
    }
}

// ---------------- GraphNorm stats: one pass sum + sumsq ----------------
#define GN_SPLIT 4
__global__ void k_gnsum() {
    int g = blockIdx.x, part = blockIdx.y, j = threadIdx.x;
    int s = g_gs[g], e = g_ge[g];
    if (s >= e) return;
    int len = e - s;
    int chunk = (len + GN_SPLIT - 1) / GN_SPLIT;
    int cs = s + part * chunk;
    int ce = min(e, cs + chunk);
    if (cs >= ce) return;
    float sum = 0.f, sq = 0.f;
    for (int n = cs; n < ce; n++) {
        float v = g_x2[n * HC + j];
        sum += v; sq += v * v;
    }
    atomicAdd(&g_mean[g * HC + j], sum);
    atomicAdd(&g_var[g * HC + j], sq);
}

__global__ void k_gnfin(const float* __restrict__ mscale, const float* __restrict__ w,
                        const float* __restrict__ b) {
    int i = blockIdx.x * blockDim.x + threadIdx.x;
    if (i >= NGRAPH * HC) return;
    int g = i >> 8, j = i & 255;
    float cnt = fmaxf((float)(g_ge[g] - g_gs[g]), 1.f);
    float inv = 1.f / cnt;
    float mean = g_mean[i] * inv;
    float ex2 = g_var[i] * inv;
    float mm = mean * mscale[j];
    float var = ex2 - 2.f * mm * mean + mm * mm;
    float cA = w[j] * rsqrtf(var + 1e-5f);
    g_mean[i] = cA;
    g_var[i] = b[j] - cA * mm;
}

// ---------------- fused norm-apply + ReLU + gate MLP ----------------
#define AG_NPB 16
__global__ __launch_bounds__(256) void k_apply_gate(const int* __restrict__ batch,
                                                    const float* __restrict__ att1_w,
                                                    const float* __restrict__ att1_b,
                                                    const float* __restrict__ att2_w,
                                                    const float* __restrict__ att2_b) {
    __shared__ float wsT[HC * 16];                      // [c][k]
    __shared__ __align__(16) float hs[AG_NPB * HC];     // [nn][c]
    int j = threadIdx.x;
    for (int t = j; t < 16 * HC; t += 256) {
        int k = t >> 8, c = t & 255;
        wsT[c * 16 + k] = att1_w[t];
    }
    int n0 = blockIdx.x * AG_NPB;
    for (int nn = 0; nn < AG_NPB; nn++) {
        int n = n0 + nn;
        int g = batch[n];
        float cA = g_mean[g * HC + j];
        float cB = g_var[g * HC + j];
        float h = fmaxf(cA * g_x2[n * HC + j] + cB, 0.f);
        g_h[n * HC + j] = h;
        hs[nn * HC + j] = h;
    }
    __syncthreads();
    int nn = j >> 4, k = j & 15;
    float acc = att1_b[k];
    const float4* hp = (const float4*)&hs[nn * HC];
#pragma unroll 8
    for (int c4 = 0; c4 < HC / 4; c4++) {
        float4 v = hp[c4];
        int c = c4 * 4;
        acc += v.x * wsT[c * 16 + k] + v.y * wsT[(c + 1) * 16 + k]
             + v.z * wsT[(c + 2) * 16 + k] + v.w * wsT[(c + 3) * 16 + k];
    }
    float r = fmaxf(acc, 0.f) * att2_w[k];
#pragma unroll
    for (int o = 8; o; o >>= 1) r += __shfl_xor_sync(0xFFFFFFFFu, r, o);
    if (k == 0) g_gate[n0 + nn] = 1.f / (1.f + __expf(-(r + att2_b[0])));
}

// ---------------- softmax pool: 4 blocks per graph ----------------
#define PL_SPLIT 4
__global__ void k_poolg() {
    int g = blockIdx.x, part = blockIdx.y, tid = threadIdx.x;
    int s = g_gs[g], e = g_ge[g];
    if (s >= e) return;
    __shared__ float red[256];

    float m = -INFINITY;
    for (int n = s + tid; n < e; n += 256) m = fmaxf(m, g_gate[n]);
    red[tid] = m; __syncthreads();
#pragma unroll
    for (int o = 128; o; o >>= 1) { if (tid < o) red[tid] = fmaxf(red[tid], red[tid + o]); __syncthreads(); }
    m = red[0]; __syncthreads();

    float sum = 0.f;
    for (int n = s + tid; n < e; n += 256) sum += __expf(g_gate[n] - m);
    red[tid] = sum; __syncthreads();
#pragma unroll
    for (int o = 128; o; o >>= 1) { if (tid < o) red[tid] += red[tid + o]; __syncthreads(); }
    float inv = 1.f / (red[0] + 1e-16f);

    int len = e - s;
    int chunk = (len + PL_SPLIT - 1) / PL_SPLIT;
    int cs = s + part * chunk;
    int ce = min(e, cs + chunk);
    if (cs >= ce) return;
    float acc = 0.f;
    for (int n = cs; n < ce; n++) {
        float wgt = __expf(g_gate[n] - m) * inv;
        acc += wgt * g_h[n * HC + tid];
    }
    atomicAdd(&g_pool[g * HC + tid], acc);
}

// ---------------- head ----------------
__global__ void k_head(const float* __restrict__ fc1_w, const float* __restrict__ fc1_b,
                       const float* __restrict__ out_w, const float* __restrict__ out_b,
                       float* __restrict__ out) {
    int g = blockIdx.x, o = threadIdx.x;  // 128 threads
    float acc = fc1_b[o];
    const float* p = &g_pool[g * HC];
    const float* w = &fc1_w[o * HC];
#pragma unroll 8
    for (int c = 0; c < HC; c++) acc += p[c] * w[c];
    acc = fmaxf(acc, 0.f) * out_w[o];
    __shared__ float red[ODIM];
    red[o] = acc;
    __syncthreads();
#pragma unroll
    for (int s = 64; s; s >>= 1) {
        if (o < s) red[o] += red[o + s];
        __syncthreads();
    }
    if (o == 0) out[g] = 1.f / (1.f + __expf(-(red[0] + out_b[0])));
}

// ---------------- launch ----------------
extern "C" void kernel_launch(void* const* d_in, const int* in_sizes, int n_in,
                              void* d_out, int out_size) {
    const float* x        = (const float*)d_in[0];
    const int*   ei       = (const int*)  d_in[1];
    const int*   batch    = (const int*)  d_in[2];
    const float* lin_w    = (const float*)d_in[3];
    const float* att_src  = (const float*)d_in[4];
    const float* att_dst  = (const float*)d_in[5];
    const float* gat_bias = (const float*)d_in[6];
    const float* gn_w     = (const float*)d_in[7];
    const float* gn_b     = (const float*)d_in[8];
    const float* gn_ms    = (const float*)d_in[9];
    const float* fc1_w    = (const float*)d_in[10];
    const float* fc1_b    = (const float*)d_in[11];
    const float* out_w    = (const float*)d_in[12];
    const float* out_b    = (const float*)d_in[13];
    const float* att1_w   = (const float*)d_in[14];
    const float* att1_b   = (const float*)d_in[15];
    const float* att2_w   = (const float*)d_in[16];
    const float* att2_b   = (const float*)d_in[17];

    float* out   = (float*)d_out;
    float* alpha = out + NGRAPH;   // [NTOT, HEADS]

    k_init<<<(NGRAPH * HC + 255) / 256, 256>>>();
    k_lin<<<(N_NODES + LIN_NPB - 1) / LIN_NPB, 256>>>(x, lin_w, att_src, att_dst);
    k_hist<<<(NTOT + 255) / 256, 256>>>(ei);
    k_scan<<<1, 1024>>>();
    k_fill<<<(NTOT + 255) / 256, 256>>>(ei);
    k_bounds<<<(N_NODES + 255) / 256, 256>>>(batch);
    k_gat<<<(N_NODES + GAT_WARPS - 1) / GAT_WARPS, 256>>>(ei, alpha, gat_bias);
    k_gnsum<<<dim3(NGRAPH, GN_SPLIT), 256>>>();
    k_gnfin<<<(NGRAPH * HC + 255) / 256, 256>>>(gn_ms, gn_w, gn_b);
    k_apply_gate<<<N_NODES / AG_NPB, 256>>>(batch, att1_w, att1_b, att2_w, att2_b);
    k_poolg<<<dim3(NGRAPH, PL_SPLIT), 256>>>();
    k_head<<<NGRAPH, ODIM>>>(fc1_w, fc1_b, out_w, out_b, out);
}

// round 4
// speedup vs baseline: 4.9941x; 1.3607x over previous
#include <cuda_runtime.h>
#include <math.h>

#define N_NODES 50000
#define N_EDGES 800000
#define NTOT    850000   // E + N self loops
#define NGRAPH  256
#define F_IN    64
#define HEADS   4
#define HC      256      // HEADS*F_IN
#define ODIM    128
#define NBLK_SCAN 196    // ceil(N_NODES/256)

// ---------------- scratch (device globals; no allocation) ----------------
__device__ float g_s   [N_NODES * HC];    // per-head weighted x sums, then unused
__device__ float g_asrc[N_NODES * HEADS];
__device__ float g_adst[N_NODES * HEADS];
__device__ float g_x2  [N_NODES * HC];    // GAT output
__device__ float g_h   [N_NODES * HC];    // after norm + relu
__device__ float g_gate[N_NODES];
__device__ float g_pool[NGRAPH * HC];
__device__ float g_mean[NGRAPH * HC];     // sum -> coefA
__device__ float g_var [NGRAPH * HC];     // sumsq -> coefB
__device__ float g_wsrc[HC];              // W_h^T att_src_h
__device__ float g_wdst[HC];
__device__ int   g_deg [N_NODES];
__device__ int   g_rowptr[N_NODES + 1];
__device__ int   g_woff[N_NODES];
__device__ int   g_csr [NTOT];
__device__ int   g_blk [256];
__device__ int   g_gs  [NGRAPH];
__device__ int   g_ge  [NGRAPH];

// ---------------- init ----------------
__global__ void k_init() {
    int i = blockIdx.x * blockDim.x + threadIdx.x;
    if (i < N_NODES) g_deg[i] = 0;
    if (i < NGRAPH * HC) { g_mean[i] = 0.f; g_var[i] = 0.f; g_pool[i] = 0.f; }
    if (i < NGRAPH) { g_gs[i] = N_NODES; g_ge[i] = 0; }
}

// ---------------- precompute projected attention vectors ----------------
__global__ void k_prew(const float* __restrict__ lin_w,
                       const float* __restrict__ att_src,
                       const float* __restrict__ att_dst) {
    int t = threadIdx.x;          // t = h*64 + c
    int h = t >> 6, c = t & 63;
    float as = 0.f, ad = 0.f;
    for (int j = 0; j < F_IN; j++) {
        float w = lin_w[(h * F_IN + j) * F_IN + c];
        as += att_src[h * F_IN + j] * w;
        ad += att_dst[h * F_IN + j] * w;
    }
    g_wsrc[t] = as;
    g_wdst[t] = ad;
}

// ---------------- scores: warp per node, a = w~ . x[n] ----------------
__global__ __launch_bounds__(256) void k_scores(const float* __restrict__ x) {
    int warp = threadIdx.x >> 5, lane = threadIdx.x & 31;
    int n = blockIdx.x * 8 + warp;
    if (n >= N_NODES) return;
    float2 xv = *(const float2*)&x[n * F_IN + lane * 2];
    float p0, p1, p2, p3, q0, q1, q2, q3;
    {
        float2 w;
        w = *(const float2*)&g_wsrc[0 * 64 + lane * 2]; p0 = w.x * xv.x + w.y * xv.y;
        w = *(const float2*)&g_wsrc[1 * 64 + lane * 2]; p1 = w.x * xv.x + w.y * xv.y;
        w = *(const float2*)&g_wsrc[2 * 64 + lane * 2]; p2 = w.x * xv.x + w.y * xv.y;
        w = *(const float2*)&g_wsrc[3 * 64 + lane * 2]; p3 = w.x * xv.x + w.y * xv.y;
        w = *(const float2*)&g_wdst[0 * 64 + lane * 2]; q0 = w.x * xv.x + w.y * xv.y;
        w = *(const float2*)&g_wdst[1 * 64 + lane * 2]; q1 = w.x * xv.x + w.y * xv.y;
        w = *(const float2*)&g_wdst[2 * 64 + lane * 2]; q2 = w.x * xv.x + w.y * xv.y;
        w = *(const float2*)&g_wdst[3 * 64 + lane * 2]; q3 = w.x * xv.x + w.y * xv.y;
    }
#pragma unroll
    for (int o = 16; o; o >>= 1) {
        p0 += __shfl_xor_sync(0xFFFFFFFFu, p0, o);
        p1 += __shfl_xor_sync(0xFFFFFFFFu, p1, o);
        p2 += __shfl_xor_sync(0xFFFFFFFFu, p2, o);
        p3 += __shfl_xor_sync(0xFFFFFFFFu, p3, o);
        q0 += __shfl_xor_sync(0xFFFFFFFFu, q0, o);
        q1 += __shfl_xor_sync(0xFFFFFFFFu, q1, o);
        q2 += __shfl_xor_sync(0xFFFFFFFFu, q2, o);
        q3 += __shfl_xor_sync(0xFFFFFFFFu, q3, o);
    }
    if (lane == 0) {
        float4 a = {p0, p1, p2, p3};
        float4 b = {q0, q1, q2, q3};
        *(float4*)&g_asrc[n * HEADS] = a;
        *(float4*)&g_adst[n * HEADS] = b;
    }
}

// ---------------- CSR build ----------------
__global__ void k_hist(const int* __restrict__ ei) {
    int e = blockIdx.x * blockDim.x + threadIdx.x;
    if (e >= NTOT) return;
    int dst = (e < N_EDGES) ? ei[N_EDGES + e] : (e - N_EDGES);
    atomicAdd(&g_deg[dst], 1);
}

__global__ void k_scan1() {
    __shared__ int sm[256];
    int b = blockIdx.x, t = threadIdx.x;
    int idx = b * 256 + t;
    int v = (idx < N_NODES) ? g_deg[idx] : 0;
    sm[t] = v;
    __syncthreads();
#pragma unroll
    for (int o = 1; o < 256; o <<= 1) {
        int u = (t >= o) ? sm[t - o] : 0;
        __syncthreads();
        sm[t] += u;
        __syncthreads();
    }
    if (idx < N_NODES) g_rowptr[idx] = sm[t] - v;   // exclusive within block
    if (t == 255) g_blk[b] = sm[255];
}

__global__ void k_scan2() {
    __shared__ int sm[256];
    int t = threadIdx.x;
    int v = (t < NBLK_SCAN) ? g_blk[t] : 0;
    sm[t] = v;
    __syncthreads();
#pragma unroll
    for (int o = 1; o < 256; o <<= 1) {
        int u = (t >= o) ? sm[t - o] : 0;
        __syncthreads();
        sm[t] += u;
        __syncthreads();
    }
    if (t < NBLK_SCAN) g_blk[t] = sm[t] - v;        // exclusive block offsets
}

__global__ void k_scan3() {
    int idx = blockIdx.x * 256 + threadIdx.x;
    if (idx < N_NODES) {
        int r = g_rowptr[idx] + g_blk[idx >> 8];
        g_rowptr[idx] = r;
        g_woff[idx] = r;
    }
    if (idx == 0) g_rowptr[N_NODES] = NTOT;
}

__global__ void k_fill(const int* __restrict__ ei) {
    int e = blockIdx.x * blockDim.x + threadIdx.x;
    if (e >= NTOT) return;
    int dst = (e < N_EDGES) ? ei[N_EDGES + e] : (e - N_EDGES);
    int pos = atomicAdd(&g_woff[dst], 1);
    g_csr[pos] = e;
}

__global__ void k_bounds(const int* __restrict__ batch) {
    int n = blockIdx.x * blockDim.x + threadIdx.x;
    if (n >= N_NODES) return;
    int g = batch[n];
    atomicMin(&g_gs[g], n);
    atomicMax(&g_ge[g], n + 1);
}

// ---------------- fused GAT: warp per dst node; aggregate RAW x rows ----------------
#define GAT_WARPS 8
#define GAT_CAP   128
__global__ __launch_bounds__(256) void k_gat(const int* __restrict__ ei,
                                             const float* __restrict__ x,
                                             float* __restrict__ alpha) {
    __shared__ int   s_e  [GAT_WARPS][GAT_CAP];
    __shared__ int   s_src[GAT_WARPS][GAT_CAP];
    __shared__ __align__(16) float s_al[GAT_WARPS][GAT_CAP * 4];
    int warp = threadIdx.x >> 5;
    int lane = threadIdx.x & 31;
    int n = blockIdx.x * GAT_WARPS + warp;
    if (n >= N_NODES) return;
    int start = g_rowptr[n], end = g_rowptr[n + 1];
    int d = end - start;

    float ad[4];
    *(float4*)ad = *(const float4*)&g_adst[n * HEADS];

    float m0 = -INFINITY, m1 = -INFINITY, m2 = -INFINITY, m3 = -INFINITY;
    float s0 = 0.f, s1 = 0.f, s2 = 0.f, s3 = 0.f;
    int c0 = lane * 2;

    if (d <= GAT_CAP) {
        for (int li = lane; li < d; li += 32) {
            int e = g_csr[start + li];
            int src = (e < N_EDGES) ? ei[e] : (e - N_EDGES);
            s_e[warp][li] = e; s_src[warp][li] = src;
            float as[4];
            *(float4*)as = *(const float4*)&g_asrc[src * HEADS];
            float4 rv; float v;
            v = as[0] + ad[0]; rv.x = (v > 0.f) ? v : 0.2f * v; m0 = fmaxf(m0, rv.x);
            v = as[1] + ad[1]; rv.y = (v > 0.f) ? v : 0.2f * v; m1 = fmaxf(m1, rv.y);
            v = as[2] + ad[2]; rv.z = (v > 0.f) ? v : 0.2f * v; m2 = fmaxf(m2, rv.z);
            v = as[3] + ad[3]; rv.w = (v > 0.f) ? v : 0.2f * v; m3 = fmaxf(m3, rv.w);
            *(float4*)&s_al[warp][li * 4] = rv;
        }
#pragma unroll
        for (int o = 16; o; o >>= 1) {
            m0 = fmaxf(m0, __shfl_xor_sync(0xFFFFFFFFu, m0, o));
            m1 = fmaxf(m1, __shfl_xor_sync(0xFFFFFFFFu, m1, o));
            m2 = fmaxf(m2, __shfl_xor_sync(0xFFFFFFFFu, m2, o));
            m3 = fmaxf(m3, __shfl_xor_sync(0xFFFFFFFFu, m3, o));
        }
        __syncwarp();
        for (int li = lane; li < d; li += 32) {
            float4 rv = *(float4*)&s_al[warp][li * 4];
            rv.x = __expf(rv.x - m0); s0 += rv.x;
            rv.y = __expf(rv.y - m1); s1 += rv.y;
            rv.z = __expf(rv.z - m2); s2 += rv.z;
            rv.w = __expf(rv.w - m3); s3 += rv.w;
            *(float4*)&s_al[warp][li * 4] = rv;
        }
#pragma unroll
        for (int o = 16; o; o >>= 1) {
            s0 += __shfl_xor_sync(0xFFFFFFFFu, s0, o);
            s1 += __shfl_xor_sync(0xFFFFFFFFu, s1, o);
            s2 += __shfl_xor_sync(0xFFFFFFFFu, s2, o);
            s3 += __shfl_xor_sync(0xFFFFFFFFu, s3, o);
        }
        float i0 = 1.f / (s0 + 1e-16f), i1 = 1.f / (s1 + 1e-16f);
        float i2 = 1.f / (s2 + 1e-16f), i3 = 1.f / (s3 + 1e-16f);
        __syncwarp();
        for (int li = lane; li < d; li += 32) {
            float4 av = *(float4*)&s_al[warp][li * 4];
            av.x *= i0; av.y *= i1; av.z *= i2; av.w *= i3;
            *(float4*)&s_al[warp][li * 4] = av;
            *(float4*)&alpha[s_e[warp][li] * 4] = av;
        }
        __syncwarp();
        // aggregate raw x rows: lane owns channels c0,c0+1; 4 head accumulators
        float2 a0 = {0.f,0.f}, a1 = {0.f,0.f}, a2 = {0.f,0.f}, a3 = {0.f,0.f};
        for (int li = 0; li < d; li++) {
            int src = s_src[warp][li];
            float2 xv = *(const float2*)&x[src * F_IN + c0];
            float w0 = s_al[warp][li * 4 + 0];
            float w1 = s_al[warp][li * 4 + 1];
            float w2 = s_al[warp][li * 4 + 2];
            float w3 = s_al[warp][li * 4 + 3];
            a0.x += w0 * xv.x; a0.y += w0 * xv.y;
            a1.x += w1 * xv.x; a1.y += w1 * xv.y;
            a2.x += w2 * xv.x; a2.y += w2 * xv.y;
            a3.x += w3 * xv.x; a3.y += w3 * xv.y;
        }
        *(float2*)&g_s[n * HC + 0 * 64 + c0] = a0;
        *(float2*)&g_s[n * HC + 1 * 64 + c0] = a1;
        *(float2*)&g_s[n * HC + 2 * 64 + c0] = a2;
        *(float2*)&g_s[n * HC + 3 * 64 + c0] = a3;
    } else {
        // gmem fallback (degree > cap; essentially never for this data)
        for (int i = start + lane; i < end; i += 32) {
            int e = g_csr[i];
            int src = (e < N_EDGES) ? ei[e] : (e - N_EDGES);
            float as[4];
            *(float4*)as = *(const float4*)&g_asrc[src * HEADS];
            float v, r;
            v = as[0] + ad[0]; r = (v > 0.f) ? v : 0.2f * v; m0 = fmaxf(m0, r);
            v = as[1] + ad[1]; r = (v > 0.f) ? v : 0.2f * v; m1 = fmaxf(m1, r);
            v = as[2] + ad[2]; r = (v > 0.f) ? v : 0.2f * v; m2 = fmaxf(m2, r);
            v = as[3] + ad[3]; r = (v > 0.f) ? v : 0.2f * v; m3 = fmaxf(m3, r);
        }
#pragma unroll
        for (int o = 16; o; o >>= 1) {
            m0 = fmaxf(m0, __shfl_xor_sync(0xFFFFFFFFu, m0, o));
            m1 = fmaxf(m1, __shfl_xor_sync(0xFFFFFFFFu, m1, o));
            m2 = fmaxf(m2, __shfl_xor_sync(0xFFFFFFFFu, m2, o));
            m3 = fmaxf(m3, __shfl_xor_sync(0xFFFFFFFFu, m3, o));
        }
        for (int i = start + lane; i < end; i += 32) {
            int e = g_csr[i];
            int src = (e < N_EDGES) ? ei[e] : (e - N_EDGES);
            float as[4];
            *(float4*)as = *(const float4*)&g_asrc[src * HEADS];
            float v, r; float4 av;
            v = as[0] + ad[0]; r = (v > 0.f) ? v : 0.2f * v; av.x = __expf(r - m0); s0 += av.x;
            v = as[1] + ad[1]; r = (v > 0.f) ? v : 0.2f * v; av.y = __expf(r - m1); s1 += av.y;
            v = as[2] + ad[2]; r = (v > 0.f) ? v : 0.2f * v; av.z = __expf(r - m2); s2 += av.z;
            v = as[3] + ad[3]; r = (v > 0.f) ? v : 0.2f * v; av.w = __expf(r - m3); s3 += av.w;
            *(float4*)&alpha[e * 4] = av;
        }
#pragma unroll
        for (int o = 16; o; o >>= 1) {
            s0 += __shfl_xor_sync(0xFFFFFFFFu, s0, o);
            s1 += __shfl_xor_sync(0xFFFFFFFFu, s1, o);
            s2 += __shfl_xor_sync(0xFFFFFFFFu, s2, o);
            s3 += __shfl_xor_sync(0xFFFFFFFFu, s3, o);
        }
        float i0 = 1.f / (s0 + 1e-16f), i1 = 1.f / (s1 + 1e-16f);
        float i2 = 1.f / (s2 + 1e-16f), i3 = 1.f / (s3 + 1e-16f);
        for (int i = start + lane; i < end; i += 32) {
            int e = g_csr[i];
            float4 av = *(float4*)&alpha[e * 4];
            av.x *= i0; av.y *= i1; av.z *= i2; av.w *= i3;
            *(float4*)&alpha[e * 4] = av;
        }
        __threadfence_block();
        __syncwarp();
        float2 a0 = {0.f,0.f}, a1 = {0.f,0.f}, a2 = {0.f,0.f}, a3 = {0.f,0.f};
        for (int i = start; i < end; i++) {
            int e = g_csr[i];
            int src = (e < N_EDGES) ? ei[e] : (e - N_EDGES);
            float2 xv = *(const float2*)&x[src * F_IN + c0];
            float4 av = *(float4*)&alpha[e * 4];
            a0.x += av.x * xv.x; a0.y += av.x * xv.y;
            a1.x += av.y * xv.x; a1.y += av.y * xv.y;
            a2.x += av.z * xv.x; a2.y += av.z * xv.y;
            a3.x += av.w * xv.x; a3.y += av.w * xv.y;
        }
        *(float2*)&g_s[n * HC + 0 * 64 + c0] = a0;
        *(float2*)&g_s[n * HC + 1 * 64 + c0] = a1;
        *(float2*)&g_s[n * HC + 2 * 64 + c0] = a2;
        *(float2*)&g_s[n * HC + 3 * 64 + c0] = a3;
    }
}

// ---------------- post-transform: x2[n,j] = W[j,:] . s[n, head(j)*64 ..] + bias ----------------
#define PO_NPB 48
__global__ __launch_bounds__(256) void k_post(const float* __restrict__ lin_w,
                                              const float* __restrict__ gat_bias) {
    __shared__ __align__(16) float ss[PO_NPB * HC];   // 48KB
    int j = threadIdx.x;
    float wreg[F_IN];
#pragma unroll
    for (int c = 0; c < F_IN; c++) wreg[c] = lin_w[j * F_IN + c];
    float bj = gat_bias[j];
    int hoff = (j >> 6) * 64;

    int n0 = blockIdx.x * PO_NPB;
    int nmax = min(PO_NPB, N_NODES - n0);
    for (int t = j; t < nmax * HC; t += 256) ss[t] = g_s[n0 * HC + t];
    __syncthreads();

    for (int nn = 0; nn < nmax; nn++) {
        const float4* sp = (const float4*)&ss[nn * HC + hoff];
        float acc = 0.f;
#pragma unroll
        for (int c4 = 0; c4 < F_IN / 4; c4++) {
            float4 v = sp[c4];
            acc += v.x * wreg[4 * c4] + v.y * wreg[4 * c4 + 1]
                 + v.z * wreg[4 * c4 + 2] + v.w * wreg[4 * c4 + 3];
        }
        g_x2[(n0 + nn) * HC + j] = acc + bj;
    }
}

// ---------------- GraphNorm stats ----------------
#define GN_SPLIT 4
__global__ void k_gnsum() {
    int g = blockIdx.x, part = blockIdx.y, j = threadIdx.x;
    int s = g_gs[g], e = g_ge[g];
    if (s >= e) return;
    int len = e - s;
    int chunk = (len + GN_SPLIT - 1) / GN_SPLIT;
    int cs = s + part * chunk;
    int ce = min(e, cs + chunk);
    if (cs >= ce) return;
    float sum = 0.f, sq = 0.f;
    for (int n = cs; n < ce; n++) {
        float v = g_x2[n * HC + j];
        sum += v; sq += v * v;
    }
    atomicAdd(&g_mean[g * HC + j], sum);
    atomicAdd(&g_var[g * HC + j], sq);
}

__global__ void k_gnfin(const float* __restrict__ mscale, const float* __restrict__ w,
                        const float* __restrict__ b) {
    int i = blockIdx.x * blockDim.x + threadIdx.x;
    if (i >= NGRAPH * HC) return;
    int g = i >> 8, j = i & 255;
    float cnt = fmaxf((float)(g_ge[g] - g_gs[g]), 1.f);
    float inv = 1.f / cnt;
    float mean = g_mean[i] * inv;
    float ex2 = g_var[i] * inv;
    float mm = mean * mscale[j];
    float var = ex2 - 2.f * mm * mean + mm * mm;
    float cA = w[j] * rsqrtf(var + 1e-5f);
    g_mean[i] = cA;
    g_var[i] = b[j] - cA * mm;
}

// ---------------- fused norm-apply + ReLU + gate MLP ----------------
#define AG_NPB 16
__global__ __launch_bounds__(256) void k_apply_gate(const int* __restrict__ batch,
                                                    const float* __restrict__ att1_w,
                                                    const float* __restrict__ att1_b,
                                                    const float* __restrict__ att2_w,
                                                    const float* __restrict__ att2_b) {
    __shared__ float wsT[HC * 16];                      // [c][k]
    __shared__ __align__(16) float hs[AG_NPB * HC];
    int j = threadIdx.x;
    for (int t = j; t < 16 * HC; t += 256) {
        int k = t >> 8, c = t & 255;
        wsT[c * 16 + k] = att1_w[t];
    }
    int n0 = blockIdx.x * AG_NPB;
    for (int nn = 0; nn < AG_NPB; nn++) {
        int n = n0 + nn;
        int g = batch[n];
        float cA = g_mean[g * HC + j];
        float cB = g_var[g * HC + j];
        float h = fmaxf(cA * g_x2[n * HC + j] + cB, 0.f);
        g_h[n * HC + j] = h;
        hs[nn * HC + j] = h;
    }
    __syncthreads();
    int nn = j >> 4, k = j & 15;
    float acc = att1_b[k];
    const float4* hp = (const float4*)&hs[nn * HC];
#pragma unroll 8
    for (int c4 = 0; c4 < HC / 4; c4++) {
        float4 v = hp[c4];
        int c = c4 * 4;
        acc += v.x * wsT[c * 16 + k] + v.y * wsT[(c + 1) * 16 + k]
             + v.z * wsT[(c + 2) * 16 + k] + v.w * wsT[(c + 3) * 16 + k];
    }
    float r = fmaxf(acc, 0.f) * att2_w[k];
#pragma unroll
    for (int o = 8; o; o >>= 1) r += __shfl_xor_sync(0xFFFFFFFFu, r, o);
    if (k == 0) g_gate[n0 + nn] = 1.f / (1.f + __expf(-(r + att2_b[0])));
}

// ---------------- softmax pool: 4 blocks per graph ----------------
#define PL_SPLIT 4
__global__ void k_poolg() {
    int g = blockIdx.x, part = blockIdx.y, tid = threadIdx.x;
    int s = g_gs[g], e = g_ge[g];
    if (s >= e) return;
    __shared__ float red[256];

    float m = -INFINITY;
    for (int n = s + tid; n < e; n += 256) m = fmaxf(m, g_gate[n]);
    red[tid] = m; __syncthreads();
#pragma unroll
    for (int o = 128; o; o >>= 1) { if (tid < o) red[tid] = fmaxf(red[tid], red[tid + o]); __syncthreads(); }
    m = red[0]; __syncthreads();

    float sum = 0.f;
    for (int n = s + tid; n < e; n += 256) sum += __expf(g_gate[n] - m);
    red[tid] = sum; __syncthreads();
#pragma unroll
    for (int o = 128; o; o >>= 1) { if (tid < o) red[tid] += red[tid + o]; __syncthreads(); }
    float inv = 1.f / (red[0] + 1e-16f);

    int len = e - s;
    int chunk = (len + PL_SPLIT - 1) / PL_SPLIT;
    int cs = s + part * chunk;
    int ce = min(e, cs + chunk);
    if (cs >= ce) return;
    float acc = 0.f;
    for (int n = cs; n < ce; n++) {
        float wgt = __expf(g_gate[n] - m) * inv;
        acc += wgt * g_h[n * HC + tid];
    }
    atomicAdd(&g_pool[g * HC + tid], acc);
}

// ---------------- head ----------------
__global__ void k_head(const float* __restrict__ fc1_w, const float* __restrict__ fc1_b,
                       const float* __restrict__ out_w, const float* __restrict__ out_b,
                       float* __restrict__ out) {
    int g = blockIdx.x, o = threadIdx.x;  // 128 threads
    float acc = fc1_b[o];
    const float* p = &g_pool[g * HC];
    const float* w = &fc1_w[o * HC];
#pragma unroll 8
    for (int c = 0; c < HC; c++) acc += p[c] * w[c];
    acc = fmaxf(acc, 0.f) * out_w[o];
    __shared__ float red[ODIM];
    red[o] = acc;
    __syncthreads();
#pragma unroll
    for (int s = 64; s; s >>= 1) {
        if (o < s) red[o] += red[o + s];
        __syncthreads();
    }
    if (o == 0) out[g] = 1.f / (1.f + __expf(-(red[0] + out_b[0])));
}

// ---------------- launch ----------------
extern "C" void kernel_launch(void* const* d_in, const int* in_sizes, int n_in,
                              void* d_out, int out_size) {
    const float* x        = (const float*)d_in[0];
    const int*   ei       = (const int*)  d_in[1];
    const int*   batch    = (const int*)  d_in[2];
    const float* lin_w    = (const float*)d_in[3];
    const float* att_src  = (const float*)d_in[4];
    const float* att_dst  = (const float*)d_in[5];
    const float* gat_bias = (const float*)d_in[6];
    const float* gn_w     = (const float*)d_in[7];
    const float* gn_b     = (const float*)d_in[8];
    const float* gn_ms    = (const float*)d_in[9];
    const float* fc1_w    = (const float*)d_in[10];
    const float* fc1_b    = (const float*)d_in[11];
    const float* out_w    = (const float*)d_in[12];
    const float* out_b    = (const float*)d_in[13];
    const float* att1_w   = (const float*)d_in[14];
    const float* att1_b   = (const float*)d_in[15];
    const float* att2_w   = (const float*)d_in[16];
    const float* att2_b   = (const float*)d_in[17];

    float* out   = (float*)d_out;
    float* alpha = out + NGRAPH;   // [NTOT, HEADS]

    k_init<<<(NGRAPH * HC + 255) / 256, 256>>>();
    k_prew<<<1, 256>>>(lin_w, att_src, att_dst);
    k_scores<<<(N_NODES + 7) / 8, 256>>>(x);
    k_hist<<<(NTOT + 255) / 256, 256>>>(ei);
    k_scan1<<<NBLK_SCAN, 256>>>();
    k_scan2<<<1, 256>>>();
    k_scan3<<<NBLK_SCAN, 256>>>();
    k_fill<<<(NTOT + 255) / 256, 256>>>(ei);
    k_bounds<<<(N_NODES + 255) / 256, 256>>>(batch);
    k_gat<<<(N_NODES + GAT_WARPS - 1) / GAT_WARPS, 256>>>(ei, x, alpha);
    k_post<<<(N_NODES + PO_NPB - 1) / PO_NPB, 256>>>(lin_w, gat_bias);
    k_gnsum<<<dim3(NGRAPH, GN_SPLIT), 256>>>();
    k_gnfin<<<(NGRAPH * HC + 255) / 256, 256>>>(gn_ms, gn_w, gn_b);
    k_apply_gate<<<N_NODES / AG_NPB, 256>>>(batch, att1_w, att1_b, att2_w, att2_b);
    k_poolg<<<dim3(NGRAPH, PL_SPLIT), 256>>>();
    k_head<<<NGRAPH, ODIM>>>(fc1_w, fc1_b, out_w, out_b, out);
}

// round 6
// speedup vs baseline: 5.4572x; 1.0927x over previous
#include <cuda_runtime.h>
#include <math.h>

#define N_NODES 50000
#define N_EDGES 800000
#define NTOT    850000   // E + N self loops
#define NGRAPH  256
#define F_IN    64
#define HEADS   4
#define HC      256      // HEADS*F_IN
#define ODIM    128
#define NBLK_SCAN 196    // ceil(N_NODES/256)

// ---------------- scratch (device globals; no allocation) ----------------
__device__ float g_s   [N_NODES * HC];    // per-head weighted x sums
__device__ float g_asrc[N_NODES * HEADS];
__device__ float g_adst[N_NODES * HEADS];
__device__ float g_x2  [N_NODES * HC];    // GAT output
__device__ float g_pool[NGRAPH * HC];     // sum exp(gate)*h
__device__ float g_gden[NGRAPH];          // sum exp(gate)
__device__ float g_mean[NGRAPH * HC];     // raw sum of x2
__device__ float g_var [NGRAPH * HC];     // raw sumsq of x2
__device__ float g_wsrc[HC];              // W_h^T att_src_h
__device__ float g_wdst[HC];
__device__ int   g_deg [N_NODES];
__device__ int   g_rowptr[N_NODES + 1];
__device__ int   g_woff[N_NODES];
__device__ int   g_csr [NTOT];
__device__ int   g_blk [256];
__device__ int   g_gs  [NGRAPH];
__device__ int   g_ge  [NGRAPH];

// ---------------- init ----------------
__global__ void k_init() {
    int i = blockIdx.x * blockDim.x + threadIdx.x;
    if (i < N_NODES) g_deg[i] = 0;
    if (i < NGRAPH * HC) { g_mean[i] = 0.f; g_var[i] = 0.f; g_pool[i] = 0.f; }
    if (i < NGRAPH) { g_gs[i] = N_NODES; g_ge[i] = 0; g_gden[i] = 0.f; }
}

// ---------------- precompute projected attention vectors ----------------
__global__ void k_prew(const float* __restrict__ lin_w,
                       const float* __restrict__ att_src,
                       const float* __restrict__ att_dst) {
    int t = threadIdx.x;          // t = h*64 + c
    int h = t >> 6, c = t & 63;
    float as = 0.f, ad = 0.f;
    for (int j = 0; j < F_IN; j++) {
        float w = lin_w[(h * F_IN + j) * F_IN + c];
        as += att_src[h * F_IN + j] * w;
        ad += att_dst[h * F_IN + j] * w;
    }
    g_wsrc[t] = as;
    g_wdst[t] = ad;
}

// ---------------- front: scores + hist + bounds in one grid ----------------
#define SC_BLKS 6250
#define HI_BLKS 3321
#define BD_BLKS 196
__global__ __launch_bounds__(256) void k_front(const float* __restrict__ x,
                                               const int* __restrict__ ei,
                                               const int* __restrict__ batch) {
    int b = blockIdx.x;
    if (b < SC_BLKS) {
        // scores: warp per node
        int warp = threadIdx.x >> 5, lane = threadIdx.x & 31;
        int n = b * 8 + warp;
        if (n >= N_NODES) return;
        float2 xv = *(const float2*)&x[n * F_IN + lane * 2];
        float p0, p1, p2, p3, q0, q1, q2, q3;
        {
            float2 w;
            w = *(const float2*)&g_wsrc[0 * 64 + lane * 2]; p0 = w.x * xv.x + w.y * xv.y;
            w = *(const float2*)&g_wsrc[1 * 64 + lane * 2]; p1 = w.x * xv.x + w.y * xv.y;
            w = *(const float2*)&g_wsrc[2 * 64 + lane * 2]; p2 = w.x * xv.x + w.y * xv.y;
            w = *(const float2*)&g_wsrc[3 * 64 + lane * 2]; p3 = w.x * xv.x + w.y * xv.y;
            w = *(const float2*)&g_wdst[0 * 64 + lane * 2]; q0 = w.x * xv.x + w.y * xv.y;
            w = *(const float2*)&g_wdst[1 * 64 + lane * 2]; q1 = w.x * xv.x + w.y * xv.y;
            w = *(const float2*)&g_wdst[2 * 64 + lane * 2]; q2 = w.x * xv.x + w.y * xv.y;
            w = *(const float2*)&g_wdst[3 * 64 + lane * 2]; q3 = w.x * xv.x + w.y * xv.y;
        }
#pragma unroll
        for (int o = 16; o; o >>= 1) {
            p0 += __shfl_xor_sync(0xFFFFFFFFu, p0, o);
            p1 += __shfl_xor_sync(0xFFFFFFFFu, p1, o);
            p2 += __shfl_xor_sync(0xFFFFFFFFu, p2, o);
            p3 += __shfl_xor_sync(0xFFFFFFFFu, p3, o);
            q0 += __shfl_xor_sync(0xFFFFFFFFu, q0, o);
            q1 += __shfl_xor_sync(0xFFFFFFFFu, q1, o);
            q2 += __shfl_xor_sync(0xFFFFFFFFu, q2, o);
            q3 += __shfl_xor_sync(0xFFFFFFFFu, q3, o);
        }
        if (lane == 0) {
            float4 a = {p0, p1, p2, p3};
            float4 bb = {q0, q1, q2, q3};
            *(float4*)&g_asrc[n * HEADS] = a;
            *(float4*)&g_adst[n * HEADS] = bb;
        }
    } else if (b < SC_BLKS + HI_BLKS) {
        int e = (b - SC_BLKS) * 256 + threadIdx.x;
        if (e >= NTOT) return;
        int dst = (e < N_EDGES) ? ei[N_EDGES + e] : (e - N_EDGES);
        atomicAdd(&g_deg[dst], 1);
    } else {
        int n = (b - SC_BLKS - HI_BLKS) * 256 + threadIdx.x;
        if (n >= N_NODES) return;
        int g = batch[n];
        atomicMin(&g_gs[g], n);
        atomicMax(&g_ge[g], n + 1);
    }
}

// ---------------- CSR scan ----------------
__global__ void k_scan1() {
    __shared__ int sm[256];
    int b = blockIdx.x, t = threadIdx.x;
    int idx = b * 256 + t;
    int v = (idx < N_NODES) ? g_deg[idx] : 0;
    sm[t] = v;
    __syncthreads();
#pragma unroll
    for (int o = 1; o < 256; o <<= 1) {
        int u = (t >= o) ? sm[t - o] : 0;
        __syncthreads();
        sm[t] += u;
        __syncthreads();
    }
    if (idx < N_NODES) g_rowptr[idx] = sm[t] - v;
    if (t == 255) g_blk[b] = sm[255];
}

__global__ void k_scan2() {
    __shared__ int sm[256];
    int t = threadIdx.x;
    int v = (t < NBLK_SCAN) ? g_blk[t] : 0;
    sm[t] = v;
    __syncthreads();
#pragma unroll
    for (int o = 1; o < 256; o <<= 1) {
        int u = (t >= o) ? sm[t - o] : 0;
        __syncthreads();
        sm[t] += u;
        __syncthreads();
    }
    if (t < NBLK_SCAN) g_blk[t] = sm[t] - v;
}

__global__ void k_scan3() {
    int idx = blockIdx.x * 256 + threadIdx.x;
    if (idx < N_NODES) {
        int r = g_rowptr[idx] + g_blk[idx >> 8];
        g_rowptr[idx] = r;
        g_woff[idx] = r;
    }
    if (idx == 0) g_rowptr[N_NODES] = NTOT;
}

__global__ void k_fill(const int* __restrict__ ei) {
    int e = blockIdx.x * blockDim.x + threadIdx.x;
    if (e >= NTOT) return;
    int dst = (e < N_EDGES) ? ei[N_EDGES + e] : (e - N_EDGES);
    int pos = atomicAdd(&g_woff[dst], 1);
    g_csr[pos] = e;
}

// ---------------- fused GAT: warp per dst node; aggregate RAW x rows ----------------
#define GAT_WARPS 8
#define GAT_CAP   128
__global__ __launch_bounds__(256) void k_gat(const int* __restrict__ ei,
                                             const float* __restrict__ x,
                                             float* __restrict__ alpha) {
    __shared__ int   s_e  [GAT_WARPS][GAT_CAP];
    __shared__ int   s_src[GAT_WARPS][GAT_CAP];
    __shared__ __align__(16) float s_al[GAT_WARPS][GAT_CAP * 4];
    int warp = threadIdx.x >> 5;
    int lane = threadIdx.x & 31;
    int n = blockIdx.x * GAT_WARPS + warp;
    if (n >= N_NODES) return;
    int start = g_rowptr[n], end = g_rowptr[n + 1];
    int d = end - start;

    float ad[4];
    *(float4*)ad = *(const float4*)&g_adst[n * HEADS];

    float m0 = -INFINITY, m1 = -INFINITY, m2 = -INFINITY, m3 = -INFINITY;
    float s0 = 0.f, s1 = 0.f, s2 = 0.f, s3 = 0.f;
    int c0 = lane * 2;

    if (d <= GAT_CAP) {
        for (int li = lane; li < d; li += 32) {
            int e = g_csr[start + li];
            int src = (e < N_EDGES) ? ei[e] : (e - N_EDGES);
            s_e[warp][li] = e; s_src[warp][li] = src;
            float as[4];
            *(float4*)as = *(const float4*)&g_asrc[src * HEADS];
            float4 rv; float v;
            v = as[0] + ad[0]; rv.x = (v > 0.f) ? v : 0.2f * v; m0 = fmaxf(m0, rv.x);
            v = as[1] + ad[1]; rv.y = (v > 0.f) ? v : 0.2f * v; m1 = fmaxf(m1, rv.y);
            v = as[2] + ad[2]; rv.z = (v > 0.f) ? v : 0.2f * v; m2 = fmaxf(m2, rv.z);
            v = as[3] + ad[3]; rv.w = (v > 0.f) ? v : 0.2f * v; m3 = fmaxf(m3, rv.w);
            *(float4*)&s_al[warp][li * 4] = rv;
        }
#pragma unroll
        for (int o = 16; o; o >>= 1) {
            m0 = fmaxf(m0, __shfl_xor_sync(0xFFFFFFFFu, m0, o));
            m1 = fmaxf(m1, __shfl_xor_sync(0xFFFFFFFFu, m1, o));
            m2 = fmaxf(m2, __shfl_xor_sync(0xFFFFFFFFu, m2, o));
            m3 = fmaxf(m3, __shfl_xor_sync(0xFFFFFFFFu, m3, o));
        }
        __syncwarp();
        for (int li = lane; li < d; li += 32) {
            float4 rv = *(float4*)&s_al[warp][li * 4];
            rv.x = __expf(rv.x - m0); s0 += rv.x;
            rv.y = __expf(rv.y - m1); s1 += rv.y;
            rv.z = __expf(rv.z - m2); s2 += rv.z;
            rv.w = __expf(rv.w - m3); s3 += rv.w;
            *(float4*)&s_al[warp][li * 4] = rv;
        }
#pragma unroll
        for (int o = 16; o; o >>= 1) {
            s0 += __shfl_xor_sync(0xFFFFFFFFu, s0, o);
            s1 += __shfl_xor_sync(0xFFFFFFFFu, s1, o);
            s2 += __shfl_xor_sync(0xFFFFFFFFu, s2, o);
            s3 += __shfl_xor_sync(0xFFFFFFFFu, s3, o);
        }
        float i0 = 1.f / (s0 + 1e-16f), i1 = 1.f / (s1 + 1e-16f);
        float i2 = 1.f / (s2 + 1e-16f), i3 = 1.f / (s3 + 1e-16f);
        __syncwarp();
        for (int li = lane; li < d; li += 32) {
            float4 av = *(float4*)&s_al[warp][li * 4];
            av.x *= i0; av.y *= i1; av.z *= i2; av.w *= i3;
            *(float4*)&s_al[warp][li * 4] = av;
            *(float4*)&alpha[s_e[warp][li] * 4] = av;
        }
        __syncwarp();
        float2 a0 = {0.f,0.f}, a1 = {0.f,0.f}, a2 = {0.f,0.f}, a3 = {0.f,0.f};
#pragma unroll 4
        for (int li = 0; li < d; li++) {
            int src = s_src[warp][li];
            float2 xv = *(const float2*)&x[src * F_IN + c0];
            float w0 = s_al[warp][li * 4 + 0];
            float w1 = s_al[warp][li * 4 + 1];
            float w2 = s_al[warp][li * 4 + 2];
            float w3 = s_al[warp][li * 4 + 3];
            a0.x += w0 * xv.x; a0.y += w0 * xv.y;
            a1.x += w1 * xv.x; a1.y += w1 * xv.y;
            a2.x += w2 * xv.x; a2.y += w2 * xv.y;
            a3.x += w3 * xv.x; a3.y += w3 * xv.y;
        }
        *(float2*)&g_s[n * HC + 0 * 64 + c0] = a0;
        *(float2*)&g_s[n * HC + 1 * 64 + c0] = a1;
        *(float2*)&g_s[n * HC + 2 * 64 + c0] = a2;
        *(float2*)&g_s[n * HC + 3 * 64 + c0] = a3;
    } else {
        // gmem fallback
        for (int i = start + lane; i < end; i += 32) {
            int e = g_csr[i];
            int src = (e < N_EDGES) ? ei[e] : (e - N_EDGES);
            float as[4];
            *(float4*)as = *(const float4*)&g_asrc[src * HEADS];
            float v, r;
            v = as[0] + ad[0]; r = (v > 0.f) ? v : 0.2f * v; m0 = fmaxf(m0, r);
            v = as[1] + ad[1]; r = (v > 0.f) ? v : 0.2f * v; m1 = fmaxf(m1, r);
            v = as[2] + ad[2]; r = (v > 0.f) ? v : 0.2f * v; m2 = fmaxf(m2, r);
            v = as[3] + ad[3]; r = (v > 0.f) ? v : 0.2f * v; m3 = fmaxf(m3, r);
        }
#pragma unroll
        for (int o = 16; o; o >>= 1) {
            m0 = fmaxf(m0, __shfl_xor_sync(0xFFFFFFFFu, m0, o));
            m1 = fmaxf(m1, __shfl_xor_sync(0xFFFFFFFFu, m1, o));
            m2 = fmaxf(m2, __shfl_xor_sync(0xFFFFFFFFu, m2, o));
            m3 = fmaxf(m3, __shfl_xor_sync(0xFFFFFFFFu, m3, o));
        }
        for (int i = start + lane; i < end; i += 32) {
            int e = g_csr[i];
            int src = (e < N_EDGES) ? ei[e] : (e - N_EDGES);
            float as[4];
            *(float4*)as = *(const float4*)&g_asrc[src * HEADS];
            float v, r; float4 av;
            v = as[0] + ad[0]; r = (v > 0.f) ? v : 0.2f * v; av.x = __expf(r - m0); s0 += av.x;
            v = as[1] + ad[1]; r = (v > 0.f) ? v : 0.2f * v; av.y = __expf(r - m1); s1 += av.y;
            v = as[2] + ad[2]; r = (v > 0.f) ? v : 0.2f * v; av.z = __expf(r - m2); s2 += av.z;
            v = as[3] + ad[3]; r = (v > 0.f) ? v : 0.2f * v; av.w = __expf(r - m3); s3 += av.w;
            *(float4*)&alpha[e * 4] = av;
        }
#pragma unroll
        for (int o = 16; o; o >>= 1) {
            s0 += __shfl_xor_sync(0xFFFFFFFFu, s0, o);
            s1 += __shfl_xor_sync(0xFFFFFFFFu, s1, o);
            s2 += __shfl_xor_sync(0xFFFFFFFFu, s2, o);
            s3 += __shfl_xor_sync(0xFFFFFFFFu, s3, o);
        }
        float i0 = 1.f / (s0 + 1e-16f), i1 = 1.f / (s1 + 1e-16f);
        float i2 = 1.f / (s2 + 1e-16f), i3 = 1.f / (s3 + 1e-16f);
        for (int i = start + lane; i < end; i += 32) {
            int e = g_csr[i];
            float4 av = *(float4*)&alpha[e * 4];
            av.x *= i0; av.y *= i1; av.z *= i2; av.w *= i3;
            *(float4*)&alpha[e * 4] = av;
        }
        __threadfence_block();
        __syncwarp();
        float2 a0 = {0.f,0.f}, a1 = {0.f,0.f}, a2 = {0.f,0.f}, a3 = {0.f,0.f};
        for (int i = start; i < end; i++) {
            int e = g_csr[i];
            int src = (e < N_EDGES) ? ei[e] : (e - N_EDGES);
            float2 xv = *(const float2*)&x[src * F_IN + c0];
            float4 av = *(float4*)&alpha[e * 4];
            a0.x += av.x * xv.x; a0.y += av.x * xv.y;
            a1.x += av.y * xv.x; a1.y += av.y * xv.y;
            a2.x += av.z * xv.x; a2.y += av.z * xv.y;
            a3.x += av.w * xv.x; a3.y += av.w * xv.y;
        }
        *(float2*)&g_s[n * HC + 0 * 64 + c0] = a0;
        *(float2*)&g_s[n * HC + 1 * 64 + c0] = a1;
        *(float2*)&g_s[n * HC + 2 * 64 + c0] = a2;
        *(float2*)&g_s[n * HC + 3 * 64 + c0] = a3;
    }
}

// ---------------- post-transform + fused GraphNorm stats ----------------
#define PO_NPB 48
__global__ __launch_bounds__(256) void k_post_gn(const float* __restrict__ lin_w,
                                                 const float* __restrict__ gat_bias,
                                                 const int* __restrict__ batch) {
    __shared__ __align__(16) float ss[PO_NPB * HC];   // 48KB
    __shared__ int sb[PO_NPB];
    int j = threadIdx.x;
    float wreg[F_IN];
#pragma unroll
    for (int c = 0; c < F_IN; c++) wreg[c] = lin_w[j * F_IN + c];
    float bj = gat_bias[j];
    int hoff = (j >> 6) * 64;

    int n0 = blockIdx.x * PO_NPB;
    int nmax = min(PO_NPB, N_NODES - n0);
    for (int t = j; t < nmax * HC; t += 256) ss[t] = g_s[n0 * HC + t];
    if (j < nmax) sb[j] = batch[n0 + j];
    __syncthreads();

    float sum = 0.f, sq = 0.f;
    int curg = sb[0];
    for (int nn = 0; nn < nmax; nn++) {
        int g = sb[nn];
        if (g != curg) {
            atomicAdd(&g_mean[curg * HC + j], sum);
            atomicAdd(&g_var[curg * HC + j], sq);
            sum = 0.f; sq = 0.f; curg = g;
        }
        const float4* sp = (const float4*)&ss[nn * HC + hoff];
        float acc = 0.f;
#pragma unroll
        for (int c4 = 0; c4 < F_IN / 4; c4++) {
            float4 v = sp[c4];
            acc += v.x * wreg[4 * c4] + v.y * wreg[4 * c4 + 1]
                 + v.z * wreg[4 * c4 + 2] + v.w * wreg[4 * c4 + 3];
        }
        acc += bj;
        g_x2[(n0 + nn) * HC + j] = acc;
        sum += acc; sq += acc * acc;
    }
    atomicAdd(&g_mean[curg * HC + j], sum);
    atomicAdd(&g_var[curg * HC + j], sq);
}

// ---------------- fused norm-apply + ReLU + gate MLP + pool accumulate ----------------
#define AG_NPB 16
__global__ __launch_bounds__(256) void k_gatepool(const int* __restrict__ batch,
                                                  const float* __restrict__ mscale,
                                                  const float* __restrict__ gw,
                                                  const float* __restrict__ gb,
                                                  const float* __restrict__ att1_w,
                                                  const float* __restrict__ att1_b,
                                                  const float* __restrict__ att2_w,
                                                  const float* __restrict__ att2_b) {
    __shared__ float wsT[HC * 16];                      // [c][k]
    __shared__ __align__(16) float hs[AG_NPB * HC];
    __shared__ float eg[AG_NPB];
    __shared__ int sb[AG_NPB];
    int j = threadIdx.x;
    for (int t = j; t < 16 * HC; t += 256) {
        int k = t >> 8, c = t & 255;
        wsT[c * 16 + k] = att1_w[t];
    }
    int n0 = blockIdx.x * AG_NPB;
    if (j < AG_NPB) sb[j] = batch[n0 + j];
    float msj = mscale[j], wj = gw[j], bj = gb[j];
    __syncthreads();

    int lastg = -1;
    float cA = 0.f, cB = 0.f;
    for (int nn = 0; nn < AG_NPB; nn++) {
        int g = sb[nn];
        if (g != lastg) {
            float cnt = fmaxf((float)(g_ge[g] - g_gs[g]), 1.f);
            float inv = 1.f / cnt;
            float mean = g_mean[g * HC + j] * inv;
            float ex2 = g_var[g * HC + j] * inv;
            float mm = mean * msj;
            float var = ex2 - 2.f * mm * mean + mm * mm;
            cA = wj * rsqrtf(var + 1e-5f);
            cB = bj - cA * mm;
            lastg = g;
        }
        float h = fmaxf(cA * g_x2[(n0 + nn) * HC + j] + cB, 0.f);
        hs[nn * HC + j] = h;
    }
    __syncthreads();

    // gate MLP: 256 threads = 16 nodes x 16 hidden
    {
        int nn = j >> 4, k = j & 15;
        float acc = att1_b[k];
        const float4* hp = (const float4*)&hs[nn * HC];
#pragma unroll 8
        for (int c4 = 0; c4 < HC / 4; c4++) {
            float4 v = hp[c4];
            int c = c4 * 4;
            acc += v.x * wsT[c * 16 + k] + v.y * wsT[(c + 1) * 16 + k]
                 + v.z * wsT[(c + 2) * 16 + k] + v.w * wsT[(c + 3) * 16 + k];
        }
        float r = fmaxf(acc, 0.f) * att2_w[k];
#pragma unroll
        for (int o = 8; o; o >>= 1) r += __shfl_xor_sync(0xFFFFFFFFu, r, o);
        if (k == 0) {
            float gate = 1.f / (1.f + __expf(-(r + att2_b[0])));
            eg[nn] = __expf(gate);
        }
    }
    __syncthreads();

    // pool accumulate: U[g] += eg*h per channel, Z[g] += eg
    float pacc = 0.f;
    int curg = sb[0];
    for (int nn = 0; nn < AG_NPB; nn++) {
        int g = sb[nn];
        if (g != curg) {
            atomicAdd(&g_pool[curg * HC + j], pacc);
            pacc = 0.f; curg = g;
        }
        pacc += eg[nn] * hs[nn * HC + j];
    }
    atomicAdd(&g_pool[curg * HC + j], pacc);
    if (j < AG_NPB) atomicAdd(&g_gden[sb[j]], eg[j]);
}

// ---------------- head: relu((U/Z)@fc1^T+b) @ out_w^T + out_b -> sigmoid ----------------
__global__ void k_head(const float* __restrict__ fc1_w, const float* __restrict__ fc1_b,
                       const float* __restrict__ out_w, const float* __restrict__ out_b,
                       float* __restrict__ out) {
    int g = blockIdx.x, o = threadIdx.x;  // 128 threads
    float invZ = 1.f / (g_gden[g] + 1e-16f);
    float acc = fc1_b[o];
    const float* p = &g_pool[g * HC];
    const float* w = &fc1_w[o * HC];
#pragma unroll 8
    for (int c = 0; c < HC; c++) acc += p[c] * invZ * w[c];
    acc = fmaxf(acc, 0.f) * out_w[o];
    __shared__ float red[ODIM];
    red[o] = acc;
    __syncthreads();
#pragma unroll
    for (int s = 64; s; s >>= 1) {
        if (o < s) red[o] += red[o + s];
        __syncthreads();
    }
    if (o == 0) out[g] = 1.f / (1.f + __expf(-(red[0] + out_b[0])));
}

// ---------------- launch ----------------
extern "C" void kernel_launch(void* const* d_in, const int* in_sizes, int n_in,
                              void* d_out, int out_size) {
    const float* x        = (const float*)d_in[0];
    const int*   ei       = (const int*)  d_in[1];
    const int*   batch    = (const int*)  d_in[2];
    const float* lin_w    = (const float*)d_in[3];
    const float* att_src  = (const float*)d_in[4];
    const float* att_dst  = (const float*)d_in[5];
    const float* gat_bias = (const float*)d_in[6];
    const float* gn_w     = (const float*)d_in[7];
    const float* gn_b     = (const float*)d_in[8];
    const float* gn_ms    = (const float*)d_in[9];
    const float* fc1_w    = (const float*)d_in[10];
    const float* fc1_b    = (const float*)d_in[11];
    const float* out_w    = (const float*)d_in[12];
    const float* out_b    = (const float*)d_in[13];
    const float* att1_w   = (const float*)d_in[14];
    const float* att1_b   = (const float*)d_in[15];
    const float* att2_w   = (const float*)d_in[16];
    const float* att2_b   = (const float*)d_in[17];

    float* out   = (float*)d_out;
    float* alpha = out + NGRAPH;   // [NTOT, HEADS]

    k_init<<<(NGRAPH * HC + 255) / 256, 256>>>();
    k_prew<<<1, 256>>>(lin_w, att_src, att_dst);
    k_front<<<SC_BLKS + HI_BLKS + BD_BLKS, 256>>>(x, ei, batch);
    k_scan1<<<NBLK_SCAN, 256>>>();
    k_scan2<<<1, 256>>>();
    k_scan3<<<NBLK_SCAN, 256>>>();
    k_fill<<<(NTOT + 255) / 256, 256>>>(ei);
    k_gat<<<(N_NODES + GAT_WARPS - 1) / GAT_WARPS, 256>>>(ei, x, alpha);
    k_post_gn<<<(N_NODES + PO_NPB - 1) / PO_NPB, 256>>>(lin_w, gat_bias, batch);
    k_gatepool<<<N_NODES / AG_NPB, 256>>>(batch, gn_ms, gn_w, gn_b,
                                          att1_w, att1_b, att2_w, att2_b);
    k_head<<<NGRAPH, ODIM>>>(fc1_w, fc1_b, out_w, out_b, out);
}

// round 7
// speedup vs baseline: 5.4588x; 1.0003x over previous
#include <cuda_runtime.h>
#include <math.h>

#define N_NODES 50000
#define N_EDGES 800000
#define NTOT    850000   // E + N self loops
#define NGRAPH  256
#define F_IN    64
#define HEADS   4
#define HC      256      // HEADS*F_IN
#define ODIM    128
#define NBLK_SCAN 196    // ceil(N_NODES/256)

// ---------------- scratch (device globals; no allocation) ----------------
__device__ float g_s   [N_NODES * HC];    // per-head weighted x sums
__device__ float g_asrc[N_NODES * HEADS];
__device__ float g_adst[N_NODES * HEADS];
__device__ float g_x2  [N_NODES * HC];    // GAT output
__device__ float g_pool[NGRAPH * HC];     // sum exp(gate)*h
__device__ float g_gden[NGRAPH];          // sum exp(gate)
__device__ float g_mean[NGRAPH * HC];     // raw sum of x2
__device__ float g_var [NGRAPH * HC];     // raw sumsq of x2
__device__ float g_wsrc[HC];              // W_h^T att_src_h
__device__ float g_wdst[HC];
__device__ int   g_deg [N_NODES];
__device__ int   g_rowptr[N_NODES + 1];
__device__ int   g_woff[N_NODES];
__device__ int2  g_csr2[NTOT];            // (edge id, src)
__device__ int   g_blk [256];
__device__ int   g_gs  [NGRAPH];
__device__ int   g_ge  [NGRAPH];

// ---------------- init (+ fused prew in last block) ----------------
__global__ void k_init(const float* __restrict__ lin_w,
                       const float* __restrict__ att_src,
                       const float* __restrict__ att_dst) {
    if (blockIdx.x == 256) {
        // prew: projected attention vectors
        int t = threadIdx.x;          // t = h*64 + c
        int h = t >> 6, c = t & 63;
        float as = 0.f, ad = 0.f;
        for (int j = 0; j < F_IN; j++) {
            float w = lin_w[(h * F_IN + j) * F_IN + c];
            as += att_src[h * F_IN + j] * w;
            ad += att_dst[h * F_IN + j] * w;
        }
        g_wsrc[t] = as;
        g_wdst[t] = ad;
        return;
    }
    int i = blockIdx.x * blockDim.x + threadIdx.x;
    if (i < N_NODES) g_deg[i] = 0;
    if (i < NGRAPH * HC) { g_mean[i] = 0.f; g_var[i] = 0.f; g_pool[i] = 0.f; }
    if (i < NGRAPH) { g_gs[i] = N_NODES; g_ge[i] = 0; g_gden[i] = 0.f; }
}

// ---------------- front: scores + hist + bounds in one grid ----------------
#define SC_BLKS 6250
#define HI_BLKS 3321
#define BD_BLKS 196
__global__ __launch_bounds__(256) void k_front(const float* __restrict__ x,
                                               const int* __restrict__ ei,
                                               const int* __restrict__ batch) {
    int b = blockIdx.x;
    if (b < SC_BLKS) {
        int warp = threadIdx.x >> 5, lane = threadIdx.x & 31;
        int n = b * 8 + warp;
        if (n >= N_NODES) return;
        float2 xv = *(const float2*)&x[n * F_IN + lane * 2];
        float p0, p1, p2, p3, q0, q1, q2, q3;
        {
            float2 w;
            w = *(const float2*)&g_wsrc[0 * 64 + lane * 2]; p0 = w.x * xv.x + w.y * xv.y;
            w = *(const float2*)&g_wsrc[1 * 64 + lane * 2]; p1 = w.x * xv.x + w.y * xv.y;
            w = *(const float2*)&g_wsrc[2 * 64 + lane * 2]; p2 = w.x * xv.x + w.y * xv.y;
            w = *(const float2*)&g_wsrc[3 * 64 + lane * 2]; p3 = w.x * xv.x + w.y * xv.y;
            w = *(const float2*)&g_wdst[0 * 64 + lane * 2]; q0 = w.x * xv.x + w.y * xv.y;
            w = *(const float2*)&g_wdst[1 * 64 + lane * 2]; q1 = w.x * xv.x + w.y * xv.y;
            w = *(const float2*)&g_wdst[2 * 64 + lane * 2]; q2 = w.x * xv.x + w.y * xv.y;
            w = *(const float2*)&g_wdst[3 * 64 + lane * 2]; q3 = w.x * xv.x + w.y * xv.y;
        }
#pragma unroll
        for (int o = 16; o; o >>= 1) {
            p0 += __shfl_xor_sync(0xFFFFFFFFu, p0, o);
            p1 += __shfl_xor_sync(0xFFFFFFFFu, p1, o);
            p2 += __shfl_xor_sync(0xFFFFFFFFu, p2, o);
            p3 += __shfl_xor_sync(0xFFFFFFFFu, p3, o);
            q0 += __shfl_xor_sync(0xFFFFFFFFu, q0, o);
            q1 += __shfl_xor_sync(0xFFFFFFFFu, q1, o);
            q2 += __shfl_xor_sync(0xFFFFFFFFu, q2, o);
            q3 += __shfl_xor_sync(0xFFFFFFFFu, q3, o);
        }
        if (lane == 0) {
            float4 a = {p0, p1, p2, p3};
            float4 bb = {q0, q1, q2, q3};
            *(float4*)&g_asrc[n * HEADS] = a;
            *(float4*)&g_adst[n * HEADS] = bb;
        }
    } else if (b < SC_BLKS + HI_BLKS) {
        int e = (b - SC_BLKS) * 256 + threadIdx.x;
        if (e >= NTOT) return;
        int dst = (e < N_EDGES) ? ei[N_EDGES + e] : (e - N_EDGES);
        atomicAdd(&g_deg[dst], 1);
    } else {
        int n = (b - SC_BLKS - HI_BLKS) * 256 + threadIdx.x;
        if (n >= N_NODES) return;
        int g = batch[n];
        atomicMin(&g_gs[g], n);
        atomicMax(&g_ge[g], n + 1);
    }
}

// ---------------- CSR scan ----------------
__global__ void k_scan1() {
    __shared__ int sm[256];
    int b = blockIdx.x, t = threadIdx.x;
    int idx = b * 256 + t;
    int v = (idx < N_NODES) ? g_deg[idx] : 0;
    sm[t] = v;
    __syncthreads();
#pragma unroll
    for (int o = 1; o < 256; o <<= 1) {
        int u = (t >= o) ? sm[t - o] : 0;
        __syncthreads();
        sm[t] += u;
        __syncthreads();
    }
    if (idx < N_NODES) g_rowptr[idx] = sm[t] - v;
    if (t == 255) g_blk[b] = sm[255];
}

__global__ void k_scan2() {
    __shared__ int sm[256];
    int t = threadIdx.x;
    int v = (t < NBLK_SCAN) ? g_blk[t] : 0;
    sm[t] = v;
    __syncthreads();
#pragma unroll
    for (int o = 1; o < 256; o <<= 1) {
        int u = (t >= o) ? sm[t - o] : 0;
        __syncthreads();
        sm[t] += u;
        __syncthreads();
    }
    if (t < NBLK_SCAN) g_blk[t] = sm[t] - v;
}

__global__ void k_scan3() {
    int idx = blockIdx.x * 256 + threadIdx.x;
    if (idx < N_NODES) {
        int r = g_rowptr[idx] + g_blk[idx >> 8];
        g_rowptr[idx] = r;
        g_woff[idx] = r;
    }
    if (idx == 0) g_rowptr[N_NODES] = NTOT;
}

__global__ void k_fill(const int* __restrict__ ei) {
    int e = blockIdx.x * blockDim.x + threadIdx.x;
    if (e >= NTOT) return;
    int src, dst;
    if (e < N_EDGES) { src = ei[e]; dst = ei[N_EDGES + e]; }
    else             { src = dst = e - N_EDGES; }
    int pos = atomicAdd(&g_woff[dst], 1);
    int2 es; es.x = e; es.y = src;
    g_csr2[pos] = es;
}

// ---------------- fused GAT: warp per dst node, register-resident ----------------
#define GAT_WARPS 8
__global__ __launch_bounds__(256) void k_gat(const float* __restrict__ x,
                                             float* __restrict__ alpha) {
    int warp = threadIdx.x >> 5;
    int lane = threadIdx.x & 31;
    int n = blockIdx.x * GAT_WARPS + warp;
    if (n >= N_NODES) return;
    int start = g_rowptr[n], end = g_rowptr[n + 1];
    int d = end - start;
    float4 ad = *(const float4*)&g_adst[n * HEADS];
    int c0 = lane * 2;

    float2 a0 = {0.f,0.f}, a1 = {0.f,0.f}, a2 = {0.f,0.f}, a3 = {0.f,0.f};

    if (d <= 32) {
        // ------- fast path: one edge per lane, all in registers -------
        int e = 0, src = 0;
        float4 rv = {-INFINITY, -INFINITY, -INFINITY, -INFINITY};
        if (lane < d) {
            int2 es = g_csr2[start + lane];
            e = es.x; src = es.y;
            float4 as = *(const float4*)&g_asrc[src * HEADS];
            float v;
            v = as.x + ad.x; rv.x = (v > 0.f) ? v : 0.2f * v;
            v = as.y + ad.y; rv.y = (v > 0.f) ? v : 0.2f * v;
            v = as.z + ad.z; rv.z = (v > 0.f) ? v : 0.2f * v;
            v = as.w + ad.w; rv.w = (v > 0.f) ? v : 0.2f * v;
        }
        float m0 = rv.x, m1 = rv.y, m2 = rv.z, m3 = rv.w;
#pragma unroll
        for (int o = 16; o; o >>= 1) {
            m0 = fmaxf(m0, __shfl_xor_sync(0xFFFFFFFFu, m0, o));
            m1 = fmaxf(m1, __shfl_xor_sync(0xFFFFFFFFu, m1, o));
            m2 = fmaxf(m2, __shfl_xor_sync(0xFFFFFFFFu, m2, o));
            m3 = fmaxf(m3, __shfl_xor_sync(0xFFFFFFFFu, m3, o));
        }
        float4 av = {0.f, 0.f, 0.f, 0.f};
        if (lane < d) {
            av.x = __expf(rv.x - m0);
            av.y = __expf(rv.y - m1);
            av.z = __expf(rv.z - m2);
            av.w = __expf(rv.w - m3);
        }
        float s0 = av.x, s1 = av.y, s2 = av.z, s3 = av.w;
#pragma unroll
        for (int o = 16; o; o >>= 1) {
            s0 += __shfl_xor_sync(0xFFFFFFFFu, s0, o);
            s1 += __shfl_xor_sync(0xFFFFFFFFu, s1, o);
            s2 += __shfl_xor_sync(0xFFFFFFFFu, s2, o);
            s3 += __shfl_xor_sync(0xFFFFFFFFu, s3, o);
        }
        av.x *= 1.f / (s0 + 1e-16f);
        av.y *= 1.f / (s1 + 1e-16f);
        av.z *= 1.f / (s2 + 1e-16f);
        av.w *= 1.f / (s3 + 1e-16f);
        if (lane < d) *(float4*)&alpha[e * 4] = av;

        // aggregation: broadcast (src, alpha) from lane li, everyone loads 2 channels
#pragma unroll 8
        for (int li = 0; li < d; li++) {
            int sb  = __shfl_sync(0xFFFFFFFFu, src, li);
            float w0 = __shfl_sync(0xFFFFFFFFu, av.x, li);
            float w1 = __shfl_sync(0xFFFFFFFFu, av.y, li);
            float w2 = __shfl_sync(0xFFFFFFFFu, av.z, li);
            float w3 = __shfl_sync(0xFFFFFFFFu, av.w, li);
            float2 xv = *(const float2*)&x[sb * F_IN + c0];
            a0.x += w0 * xv.x; a0.y += w0 * xv.y;
            a1.x += w1 * xv.x; a1.y += w1 * xv.y;
            a2.x += w2 * xv.x; a2.y += w2 * xv.y;
            a3.x += w3 * xv.x; a3.y += w3 * xv.y;
        }
    } else {
        // ------- slow path (rare): chunked, register-only, 3 passes -------
        float m0 = -INFINITY, m1 = -INFINITY, m2 = -INFINITY, m3 = -INFINITY;
        for (int i = start + lane; i < end; i += 32) {
            int2 es = g_csr2[i];
            float4 as = *(const float4*)&g_asrc[es.y * HEADS];
            float v, r;
            v = as.x + ad.x; r = (v > 0.f) ? v : 0.2f * v; m0 = fmaxf(m0, r);
            v = as.y + ad.y; r = (v > 0.f) ? v : 0.2f * v; m1 = fmaxf(m1, r);
            v = as.z + ad.z; r = (v > 0.f) ? v : 0.2f * v; m2 = fmaxf(m2, r);
            v = as.w + ad.w; r = (v > 0.f) ? v : 0.2f * v; m3 = fmaxf(m3, r);
        }
#pragma unroll
        for (int o = 16; o; o >>= 1) {
            m0 = fmaxf(m0, __shfl_xor_sync(0xFFFFFFFFu, m0, o));
            m1 = fmaxf(m1, __shfl_xor_sync(0xFFFFFFFFu, m1, o));
            m2 = fmaxf(m2, __shfl_xor_sync(0xFFFFFFFFu, m2, o));
            m3 = fmaxf(m3, __shfl_xor_sync(0xFFFFFFFFu, m3, o));
        }
        float s0 = 0.f, s1 = 0.f, s2 = 0.f, s3 = 0.f;
        for (int i = start + lane; i < end; i += 32) {
            int2 es = g_csr2[i];
            float4 as = *(const float4*)&g_asrc[es.y * HEADS];
            float v, r; float4 ev;
            v = as.x + ad.x; r = (v > 0.f) ? v : 0.2f * v; ev.x = __expf(r - m0); s0 += ev.x;
            v = as.y + ad.y; r = (v > 0.f) ? v : 0.2f * v; ev.y = __expf(r - m1); s1 += ev.y;
            v = as.z + ad.z; r = (v > 0.f) ? v : 0.2f * v; ev.z = __expf(r - m2); s2 += ev.z;
            v = as.w + ad.w; r = (v > 0.f) ? v : 0.2f * v; ev.w = __expf(r - m3); s3 += ev.w;
            *(float4*)&alpha[es.x * 4] = ev;
        }
#pragma unroll
        for (int o = 16; o; o >>= 1) {
            s0 += __shfl_xor_sync(0xFFFFFFFFu, s0, o);
            s1 += __shfl_xor_sync(0xFFFFFFFFu, s1, o);
            s2 += __shfl_xor_sync(0xFFFFFFFFu, s2, o);
            s3 += __shfl_xor_sync(0xFFFFFFFFu, s3, o);
        }
        float i0 = 1.f / (s0 + 1e-16f), i1 = 1.f / (s1 + 1e-16f);
        float i2 = 1.f / (s2 + 1e-16f), i3 = 1.f / (s3 + 1e-16f);
        for (int base = start; base < end; base += 32) {
            int li = base + lane;
            int cl = min(32, end - base);
            int src = 0; float4 av = {0.f, 0.f, 0.f, 0.f};
            if (li < end) {
                int2 es = g_csr2[li];
                src = es.y;
                av = *(float4*)&alpha[es.x * 4];
                av.x *= i0; av.y *= i1; av.z *= i2; av.w *= i3;
                *(float4*)&alpha[es.x * 4] = av;
            }
            for (int k = 0; k < cl; k++) {
                int sb  = __shfl_sync(0xFFFFFFFFu, src, k);
                float w0 = __shfl_sync(0xFFFFFFFFu, av.x, k);
                float w1 = __shfl_sync(0xFFFFFFFFu, av.y, k);
                float w2 = __shfl_sync(0xFFFFFFFFu, av.z, k);
                float w3 = __shfl_sync(0xFFFFFFFFu, av.w, k);
                float2 xv = *(const float2*)&x[sb * F_IN + c0];
                a0.x += w0 * xv.x; a0.y += w0 * xv.y;
                a1.x += w1 * xv.x; a1.y += w1 * xv.y;
                a2.x += w2 * xv.x; a2.y += w2 * xv.y;
                a3.x += w3 * xv.x; a3.y += w3 * xv.y;
            }
        }
    }
    *(float2*)&g_s[n * HC + 0 * 64 + c0] = a0;
    *(float2*)&g_s[n * HC + 1 * 64 + c0] = a1;
    *(float2*)&g_s[n * HC + 2 * 64 + c0] = a2;
    *(float2*)&g_s[n * HC + 3 * 64 + c0] = a3;
}

// ---------------- post-transform + fused GraphNorm stats ----------------
#define PO_NPB 48
__global__ __launch_bounds__(256) void k_post_gn(const float* __restrict__ lin_w,
                                                 const float* __restrict__ gat_bias,
                                                 const int* __restrict__ batch) {
    __shared__ __align__(16) float ss[PO_NPB * HC];   // 48KB
    __shared__ int sb[PO_NPB];
    int j = threadIdx.x;
    float wreg[F_IN];
#pragma unroll
    for (int c = 0; c < F_IN; c++) wreg[c] = lin_w[j * F_IN + c];
    float bj = gat_bias[j];
    int hoff = (j >> 6) * 64;

    int n0 = blockIdx.x * PO_NPB;
    int nmax = min(PO_NPB, N_NODES - n0);
    for (int t = j; t < nmax * HC; t += 256) ss[t] = g_s[n0 * HC + t];
    if (j < nmax) sb[j] = batch[n0 + j];
    __syncthreads();

    float sum = 0.f, sq = 0.f;
    int curg = sb[0];
    for (int nn = 0; nn < nmax; nn++) {
        int g = sb[nn];
        if (g != curg) {
            atomicAdd(&g_mean[curg * HC + j], sum);
            atomicAdd(&g_var[curg * HC + j], sq);
            sum = 0.f; sq = 0.f; curg = g;
        }
        const float4* sp = (const float4*)&ss[nn * HC + hoff];
        float acc = 0.f;
#pragma unroll
        for (int c4 = 0; c4 < F_IN / 4; c4++) {
            float4 v = sp[c4];
            acc += v.x * wreg[4 * c4] + v.y * wreg[4 * c4 + 1]
                 + v.z * wreg[4 * c4 + 2] + v.w * wreg[4 * c4 + 3];
        }
        acc += bj;
        g_x2[(n0 + nn) * HC + j] = acc;
        sum += acc; sq += acc * acc;
    }
    atomicAdd(&g_mean[curg * HC + j], sum);
    atomicAdd(&g_var[curg * HC + j], sq);
}

// ---------------- fused norm-apply + ReLU + gate MLP + pool accumulate ----------------
#define AG_NPB 16
__global__ __launch_bounds__(256) void k_gatepool(const int* __restrict__ batch,
                                                  const float* __restrict__ mscale,
                                                  const float* __restrict__ gw,
                                                  const float* __restrict__ gb,
                                                  const float* __restrict__ att1_w,
                                                  const float* __restrict__ att1_b,
                                                  const float* __restrict__ att2_w,
                                                  const float* __restrict__ att2_b) {
    __shared__ float wsT[HC * 16];                      // [c][k]
    __shared__ __align__(16) float hs[AG_NPB * HC];
    __shared__ float eg[AG_NPB];
    __shared__ int sb[AG_NPB];
    int j = threadIdx.x;
    for (int t = j; t < 16 * HC; t += 256) {
        int k = t >> 8, c = t & 255;
        wsT[c * 16 + k] = att1_w[t];
    }
    int n0 = blockIdx.x * AG_NPB;
    if (j < AG_NPB) sb[j] = batch[n0 + j];
    float msj = mscale[j], wj = gw[j], bj = gb[j];
    __syncthreads();

    int lastg = -1;
    float cA = 0.f, cB = 0.f;
    for (int nn = 0; nn < AG_NPB; nn++) {
        int g = sb[nn];
        if (g != lastg) {
            float cnt = fmaxf((float)(g_ge[g] - g_gs[g]), 1.f);
            float inv = 1.f / cnt;
            float mean = g_mean[g * HC + j] * inv;
            float ex2 = g_var[g * HC + j] * inv;
            float mm = mean * msj;
            float var = ex2 - 2.f * mm * mean + mm * mm;
            cA = wj * rsqrtf(var + 1e-5f);
            cB = bj - cA * mm;
            lastg = g;
        }
        float h = fmaxf(cA * g_x2[(n0 + nn) * HC + j] + cB, 0.f);
        hs[nn * HC + j] = h;
    }
    __syncthreads();

    // gate MLP: 256 threads = 16 nodes x 16 hidden
    {
        int nn = j >> 4, k = j & 15;
        float acc = att1_b[k];
        const float4* hp = (const float4*)&hs[nn * HC];
#pragma unroll 8
        for (int c4 = 0; c4 < HC / 4; c4++) {
            float4 v = hp[c4];
            int c = c4 * 4;
            acc += v.x * wsT[c * 16 + k] + v.y * wsT[(c + 1) * 16 + k]
                 + v.z * wsT[(c + 2) * 16 + k] + v.w * wsT[(c + 3) * 16 + k];
        }
        float r = fmaxf(acc, 0.f) * att2_w[k];
#pragma unroll
        for (int o = 8; o; o >>= 1) r += __shfl_xor_sync(0xFFFFFFFFu, r, o);
        if (k == 0) {
            float gate = 1.f / (1.f + __expf(-(r + att2_b[0])));
            eg[nn] = __expf(gate);
        }
    }
    __syncthreads();

    // pool accumulate: U[g] += eg*h per channel, Z[g] += eg
    float pacc = 0.f;
    int curg = sb[0];
    for (int nn = 0; nn < AG_NPB; nn++) {
        int g = sb[nn];
        if (g != curg) {
            atomicAdd(&g_pool[curg * HC + j], pacc);
            pacc = 0.f; curg = g;
        }
        pacc += eg[nn] * hs[nn * HC + j];
    }
    atomicAdd(&g_pool[curg * HC + j], pacc);
    if (j < AG_NPB) atomicAdd(&g_gden[sb[j]], eg[j]);
}

// ---------------- head: relu((U/Z)@fc1^T+b) @ out_w^T + out_b -> sigmoid ----------------
__global__ void k_head(const float* __restrict__ fc1_w, const float* __restrict__ fc1_b,
                       const float* __restrict__ out_w, const float* __restrict__ out_b,
                       float* __restrict__ out) {
    int g = blockIdx.x, o = threadIdx.x;  // 128 threads
    float invZ = 1.f / (g_gden[g] + 1e-16f);
    float acc = fc1_b[o];
    const float* p = &g_pool[g * HC];
    const float* w = &fc1_w[o * HC];
#pragma unroll 8
    for (int c = 0; c < HC; c++) acc += p[c] * invZ * w[c];
    acc = fmaxf(acc, 0.f) * out_w[o];
    __shared__ float red[ODIM];
    red[o] = acc;
    __syncthreads();
#pragma unroll
    for (int s = 64; s; s >>= 1) {
        if (o < s) red[o] += red[o + s];
        __syncthreads();
    }
    if (o == 0) out[g] = 1.f / (1.f + __expf(-(red[0] + out_b[0])));
}

// ---------------- launch ----------------
extern "C" void kernel_launch(void* const* d_in, const int* in_sizes, int n_in,
                              void* d_out, int out_size) {
    const float* x        = (const float*)d_in[0];
    const int*   ei       = (const int*)  d_in[1];
    const int*   batch    = (const int*)  d_in[2];
    const float* lin_w    = (const float*)d_in[3];
    const float* att_src  = (const float*)d_in[4];
    const float* att_dst  = (const float*)d_in[5];
    const float* gat_bias = (const float*)d_in[6];
    const float* gn_w     = (const float*)d_in[7];
    const float* gn_b     = (const float*)d_in[8];
    const float* gn_ms    = (const float*)d_in[9];
    const float* fc1_w    = (const float*)d_in[10];
    const float* fc1_b    = (const float*)d_in[11];
    const float* out_w    = (const float*)d_in[12];
    const float* out_b    = (const float*)d_in[13];
    const float* att1_w   = (const float*)d_in[14];
    const float* att1_b   = (const float*)d_in[15];
    const float* att2_w   = (const float*)d_in[16];
    const float* att2_b   = (const float*)d_in[17];

    float* out   = (float*)d_out;
    float* alpha = out + NGRAPH;   // [NTOT, HEADS]

    k_init<<<257, 256>>>(lin_w, att_src, att_dst);
    k_front<<<SC_BLKS + HI_BLKS + BD_BLKS, 256>>>(x, ei, batch);
    k_scan1<<<NBLK_SCAN, 256>>>();
    k_scan2<<<1, 256>>>();
    k_scan3<<<NBLK_SCAN, 256>>>();
    k_fill<<<(NTOT + 255) / 256, 256>>>(ei);
    k_gat<<<(N_NODES + GAT_WARPS - 1) / GAT_WARPS, 256>>>(x, alpha);
    k_post_gn<<<(N_NODES + PO_NPB - 1) / PO_NPB, 256>>>(lin_w, gat_bias, batch);
    k_gatepool<<<N_NODES / AG_NPB, 256>>>(batch, gn_ms, gn_w, gn_b,
                                          att1_w, att1_b, att2_w, att2_b);
    k_head<<<NGRAPH, ODIM>>>(fc1_w, fc1_b, out_w, out_b, out);
}